// round 1
// baseline (speedup 1.0000x reference)
#include <cuda_runtime.h>
#include <math.h>

#define NN_   10000
#define EE_   320000
#define ETOT  (EE_ + NN_)
#define H_    4
#define F_    256
#define HF_   1024
#define LEAKY 0.2f
#define CH    512   // edge chunk per aggregation pass

// ---------------- scratch (device globals; no allocation allowed) ----------
__device__ float g_h[(size_t)NN_ * HF_];        // [N,H,F] projected features
__device__ float g_als[NN_ * H_];
__device__ float g_ald[NN_ * H_];
__device__ float g_act0[(size_t)NN_ * F_];
__device__ float g_act1[(size_t)NN_ * F_];
__device__ float g_zbuf[(size_t)NN_ * F_];
__device__ int   g_cnt[NN_];
__device__ int   g_off[NN_ + 1];
__device__ int   g_wpos[NN_];
__device__ int   g_srcs[ETOT];

// ---------------- CSR build -------------------------------------------------
__global__ void zero_int2() {
    int i = blockIdx.x * blockDim.x + threadIdx.x;
    if (i < NN_) { g_cnt[i] = 0; g_wpos[i] = 0; }
}

__global__ void count_kernel(const int* __restrict__ ei) {
    int e = blockIdx.x * blockDim.x + threadIdx.x;
    if (e >= ETOT) return;
    int dst = (e < EE_) ? ei[EE_ + e] : (e - EE_);
    atomicAdd(&g_cnt[dst], 1);
}

__global__ void scan_kernel() {
    __shared__ int sh[1024];
    int tid = threadIdx.x;
    int carry = 0;
    for (int base = 0; base < NN_; base += 1024) {
        int v = (base + tid < NN_) ? g_cnt[base + tid] : 0;
        sh[tid] = v;
        __syncthreads();
        for (int d = 1; d < 1024; d <<= 1) {
            int t = (tid >= d) ? sh[tid - d] : 0;
            __syncthreads();
            sh[tid] += t;
            __syncthreads();
        }
        if (base + tid < NN_) g_off[base + tid] = carry + sh[tid] - v;
        int tot = sh[1023];
        __syncthreads();
        carry += tot;
    }
    if (tid == 0) g_off[NN_] = carry;
}

__global__ void scatter_kernel(const int* __restrict__ ei) {
    int e = blockIdx.x * blockDim.x + threadIdx.x;
    if (e >= ETOT) return;
    int src, dst;
    if (e < EE_) { src = ei[e]; dst = ei[EE_ + e]; }
    else         { src = e - EE_; dst = e - EE_; }
    int pos = g_off[dst] + atomicAdd(&g_wpos[dst], 1);
    g_srcs[pos] = src;
}

// ---------------- SGEMM NN: C[M,Nn] = A[M,K] @ B[K,Nn] ---------------------
#define BM 128
#define BN 128
#define BK 8
__global__ __launch_bounds__(256) void sgemm_nn(
    const float* __restrict__ A, const float* __restrict__ B,
    float* __restrict__ C, int M, int Nn, int K)
{
    __shared__ float As[BK][BM];
    __shared__ float Bs[BK][BN];
    int m0 = blockIdx.y * BM, n0 = blockIdx.x * BN;
    int tid = threadIdx.x;
    int rm = (tid / 16) * 8, rn = (tid % 16) * 8;
    float acc[8][8];
#pragma unroll
    for (int i = 0; i < 8; i++)
#pragma unroll
        for (int j = 0; j < 8; j++) acc[i][j] = 0.f;

    for (int k0 = 0; k0 < K; k0 += BK) {
#pragma unroll
        for (int i = tid; i < BM * BK; i += 256) {
            int r = i / BK, c = i % BK;
            int gm = m0 + r;
            As[c][r] = (gm < M) ? A[(size_t)gm * K + k0 + c] : 0.f;
        }
#pragma unroll
        for (int i = tid; i < BK * BN; i += 256) {
            int r = i / BN, c = i % BN;
            int gn = n0 + c;
            Bs[r][c] = (gn < Nn) ? B[(size_t)(k0 + r) * Nn + gn] : 0.f;
        }
        __syncthreads();
#pragma unroll
        for (int kk = 0; kk < BK; kk++) {
            float a[8], b[8];
#pragma unroll
            for (int i = 0; i < 8; i++) a[i] = As[kk][rm + i];
#pragma unroll
            for (int j = 0; j < 8; j++) b[j] = Bs[kk][rn + j];
#pragma unroll
            for (int i = 0; i < 8; i++)
#pragma unroll
                for (int j = 0; j < 8; j++) acc[i][j] += a[i] * b[j];
        }
        __syncthreads();
    }
#pragma unroll
    for (int i = 0; i < 8; i++) {
        int gm = m0 + rm + i;
        if (gm >= M) continue;
#pragma unroll
        for (int j = 0; j < 8; j++) {
            int gn = n0 + rn + j;
            if (gn < Nn) C[(size_t)gm * Nn + gn] = acc[i][j];
        }
    }
}

// ---------------- SGEMM NT + sigmoid: C = sigmoid(A @ B^T) -----------------
__global__ __launch_bounds__(256) void sgemm_nt_sig(
    const float* __restrict__ A, const float* __restrict__ B,
    float* __restrict__ C, int M, int Nn, int K)
{
    __shared__ float As[BK][BM];
    __shared__ float Bs[BK][BN];
    int m0 = blockIdx.y * BM, n0 = blockIdx.x * BN;
    int tid = threadIdx.x;
    int rm = (tid / 16) * 8, rn = (tid % 16) * 8;
    float acc[8][8];
#pragma unroll
    for (int i = 0; i < 8; i++)
#pragma unroll
        for (int j = 0; j < 8; j++) acc[i][j] = 0.f;

    for (int k0 = 0; k0 < K; k0 += BK) {
#pragma unroll
        for (int i = tid; i < BM * BK; i += 256) {
            int r = i / BK, c = i % BK;
            int gm = m0 + r;
            As[c][r] = (gm < M) ? A[(size_t)gm * K + k0 + c] : 0.f;
        }
#pragma unroll
        for (int i = tid; i < BN * BK; i += 256) {
            int r = i / BK, c = i % BK;
            int gn = n0 + r;
            Bs[c][r] = (gn < Nn) ? B[(size_t)gn * K + k0 + c] : 0.f;
        }
        __syncthreads();
#pragma unroll
        for (int kk = 0; kk < BK; kk++) {
            float a[8], b[8];
#pragma unroll
            for (int i = 0; i < 8; i++) a[i] = As[kk][rm + i];
#pragma unroll
            for (int j = 0; j < 8; j++) b[j] = Bs[kk][rn + j];
#pragma unroll
            for (int i = 0; i < 8; i++)
#pragma unroll
                for (int j = 0; j < 8; j++) acc[i][j] += a[i] * b[j];
        }
        __syncthreads();
    }
#pragma unroll
    for (int i = 0; i < 8; i++) {
        int gm = m0 + rm + i;
        if (gm >= M) continue;
#pragma unroll
        for (int j = 0; j < 8; j++) {
            int gn = n0 + rn + j;
            if (gn < Nn) {
                float v = acc[i][j];
                C[(size_t)gm * Nn + gn] = 1.f / (1.f + expf(-v));
            }
        }
    }
}

// ---------------- attention logits per (node, head) ------------------------
__global__ void attn_kernel(const float* __restrict__ a_src,
                            const float* __restrict__ a_dst)
{
    int n = blockIdx.x;
    int w = threadIdx.x / 32;      // head
    int lane = threadIdx.x % 32;
    const float* hp = &g_h[(size_t)n * HF_ + w * F_];
    float ss = 0.f, sd = 0.f;
#pragma unroll
    for (int f = lane; f < F_; f += 32) {
        float hv = hp[f];
        ss += hv * a_src[w * F_ + f];
        sd += hv * a_dst[w * F_ + f];
    }
#pragma unroll
    for (int o = 16; o; o >>= 1) {
        ss += __shfl_down_sync(0xffffffffu, ss, o);
        sd += __shfl_down_sync(0xffffffffu, sd, o);
    }
    if (lane == 0) {
        g_als[n * H_ + w] = ss;
        g_ald[n * H_ + w] = sd;
    }
}

// ---------------- per-dst segment softmax + aggregation --------------------
__device__ __forceinline__ float leaky(float x) {
    return x > 0.f ? x : LEAKY * x;
}

__global__ __launch_bounds__(256) void aggregate(
    const float* __restrict__ bias, float* __restrict__ xout, int mode /*0 relu,1 tanh*/)
{
    __shared__ float red[256];
    __shared__ float sm[H_], ssum[H_];
    __shared__ float alpha_sh[CH][H_];
    __shared__ int   src_sh[CH];

    int n = blockIdx.x, tid = threadIdx.x;
    int beg = g_off[n];
    int deg = g_off[n + 1] - beg;

    float ald[H_];
#pragma unroll
    for (int h = 0; h < H_; h++) ald[h] = g_ald[n * H_ + h];

    // pass 1: per-head max
    float mloc[H_];
#pragma unroll
    for (int h = 0; h < H_; h++) mloc[h] = -1e30f;
    for (int i = tid; i < deg; i += 256) {
        int s = g_srcs[beg + i];
#pragma unroll
        for (int h = 0; h < H_; h++) {
            float e = leaky(g_als[s * H_ + h] + ald[h]);
            mloc[h] = fmaxf(mloc[h], e);
        }
    }
#pragma unroll
    for (int h = 0; h < H_; h++) {
        red[tid] = mloc[h];
        __syncthreads();
        for (int o = 128; o; o >>= 1) {
            if (tid < o) red[tid] = fmaxf(red[tid], red[tid + o]);
            __syncthreads();
        }
        if (tid == 0) sm[h] = red[0];
        __syncthreads();
    }

    // pass 2: per-head exp-sum
    float sloc[H_] = {0.f, 0.f, 0.f, 0.f};
    for (int i = tid; i < deg; i += 256) {
        int s = g_srcs[beg + i];
#pragma unroll
        for (int h = 0; h < H_; h++) {
            float e = leaky(g_als[s * H_ + h] + ald[h]);
            sloc[h] += expf(e - sm[h]);
        }
    }
#pragma unroll
    for (int h = 0; h < H_; h++) {
        red[tid] = sloc[h];
        __syncthreads();
        for (int o = 128; o; o >>= 1) {
            if (tid < o) red[tid] += red[tid + o];
            __syncthreads();
        }
        if (tid == 0) ssum[h] = red[0];
        __syncthreads();
    }

    // pass 3: chunked alpha + weighted aggregation (thread tid owns feature tid of each head)
    float acc[H_] = {0.f, 0.f, 0.f, 0.f};
    for (int base = 0; base < deg; base += CH) {
        int c = min(CH, deg - base);
        __syncthreads();
        for (int i = tid; i < c; i += 256) {
            int s = g_srcs[beg + base + i];
            src_sh[i] = s;
#pragma unroll
            for (int h = 0; h < H_; h++) {
                float e = leaky(g_als[s * H_ + h] + ald[h]);
                alpha_sh[i][h] = expf(e - sm[h]) / (ssum[h] + 1e-16f);
            }
        }
        __syncthreads();
        for (int j = 0; j < c; j++) {
            int s = src_sh[j];
            const float* hp = &g_h[(size_t)s * HF_ + tid];
            float a0 = alpha_sh[j][0], a1 = alpha_sh[j][1];
            float a2 = alpha_sh[j][2], a3 = alpha_sh[j][3];
            acc[0] += a0 * hp[0 * F_];
            acc[1] += a1 * hp[1 * F_];
            acc[2] += a2 * hp[2 * F_];
            acc[3] += a3 * hp[3 * F_];
        }
    }

    float v = (acc[0] + acc[1] + acc[2] + acc[3]) * 0.25f + bias[tid];
    v = mode ? tanhf(v) : fmaxf(v, 0.f);
    xout[(size_t)n * F_ + tid] = v;
}

// ---------------- driver ----------------------------------------------------
extern "C" void kernel_launch(void* const* d_in, const int* in_sizes, int n_in,
                              void* d_out, int out_size)
{
    const float* x  = (const float*)d_in[0];
    const int*   ei = (const int*)d_in[1];
    const float* W[4];  const float* as_[4]; const float* ad_[4]; const float* b_[4];
    for (int l = 0; l < 4; l++) {
        W[l]   = (const float*)d_in[2 + 4 * l];
        as_[l] = (const float*)d_in[3 + 4 * l];
        ad_[l] = (const float*)d_in[4 + 4 * l];
        b_[l]  = (const float*)d_in[5 + 4 * l];
    }
    float* out = (float*)d_out;

    // resolve device scratch pointers
    float *p_h, *p_act0, *p_act1, *p_z;
    cudaGetSymbolAddress((void**)&p_h,    g_h);
    cudaGetSymbolAddress((void**)&p_act0, g_act0);
    cudaGetSymbolAddress((void**)&p_act1, g_act1);
    cudaGetSymbolAddress((void**)&p_z,    g_zbuf);

    const size_t ADJ = (size_t)NN_ * NN_;
    bool z_in_out = ((size_t)out_size >= ADJ + (size_t)NN_ * F_);
    float* zptr = z_in_out ? (out + ADJ) : p_z;

    // ---- CSR build (same for all layers) ----
    zero_int2<<<(NN_ + 255) / 256, 256>>>();
    count_kernel<<<(ETOT + 255) / 256, 256>>>(ei);
    scan_kernel<<<1, 1024>>>();
    scatter_kernel<<<(ETOT + 255) / 256, 256>>>(ei);

    // ---- 4 GAT layers ----
    const float* xin = x;
    float* xouts[4] = {p_act0, p_act1, p_act0, zptr};
    dim3 ggrid((HF_ + BN - 1) / BN, (NN_ + BM - 1) / BM);
    for (int l = 0; l < 4; l++) {
        sgemm_nn<<<ggrid, 256>>>(xin, W[l], p_h, NN_, HF_, F_);
        attn_kernel<<<NN_, H_ * 32>>>(as_[l], ad_[l]);
        aggregate<<<NN_, 256>>>(b_[l], xouts[l], (l == 3) ? 1 : 0);
        xin = xouts[l];
    }

    // ---- adj_recon = sigmoid(z @ z^T) ----
    dim3 fgrid((NN_ + BN - 1) / BN, (NN_ + BM - 1) / BM);
    sgemm_nt_sig<<<fgrid, 256>>>(zptr, zptr, out, NN_, NN_, F_);
}

// round 3
// speedup vs baseline: 1.1607x; 1.1607x over previous
#include <cuda_runtime.h>
#include <cuda_bf16.h>
#include <math.h>
#include <stdint.h>

#define NN_   10000
#define EE_   320000
#define ETOT  (EE_ + NN_)
#define H_    4
#define F_    256
#define HF_   1024
#define LEAKY 0.2f
#define CH    512   // edge chunk per aggregation pass

// ---------------- scratch (device globals; no allocation allowed) ----------
__device__ float g_h[(size_t)NN_ * HF_];        // [N,H,F] projected features
__device__ float g_als[NN_ * H_];
__device__ float g_ald[NN_ * H_];
__device__ float g_act0[(size_t)NN_ * F_];
__device__ float g_act1[(size_t)NN_ * F_];
__device__ float g_zbuf[(size_t)NN_ * F_];
__device__ int   g_cnt[NN_];
__device__ int   g_off[NN_ + 1];
__device__ int   g_wpos[NN_];
__device__ int   g_srcs[ETOT];
__device__ __align__(16) __nv_bfloat16 g_zh[(size_t)NN_ * F_];
__device__ __align__(16) __nv_bfloat16 g_zl[(size_t)NN_ * F_];

// ---------------- CSR build -------------------------------------------------
__global__ void zero_int2() {
    int i = blockIdx.x * blockDim.x + threadIdx.x;
    if (i < NN_) { g_cnt[i] = 0; g_wpos[i] = 0; }
}

__global__ void count_kernel(const int* __restrict__ ei) {
    int e = blockIdx.x * blockDim.x + threadIdx.x;
    if (e >= ETOT) return;
    int dst = (e < EE_) ? ei[EE_ + e] : (e - EE_);
    atomicAdd(&g_cnt[dst], 1);
}

__global__ void scan_kernel() {
    __shared__ int sh[1024];
    int tid = threadIdx.x;
    int carry = 0;
    for (int base = 0; base < NN_; base += 1024) {
        int v = (base + tid < NN_) ? g_cnt[base + tid] : 0;
        sh[tid] = v;
        __syncthreads();
        for (int d = 1; d < 1024; d <<= 1) {
            int t = (tid >= d) ? sh[tid - d] : 0;
            __syncthreads();
            sh[tid] += t;
            __syncthreads();
        }
        if (base + tid < NN_) g_off[base + tid] = carry + sh[tid] - v;
        int tot = sh[1023];
        __syncthreads();
        carry += tot;
    }
    if (tid == 0) g_off[NN_] = carry;
}

__global__ void scatter_kernel(const int* __restrict__ ei) {
    int e = blockIdx.x * blockDim.x + threadIdx.x;
    if (e >= ETOT) return;
    int src, dst;
    if (e < EE_) { src = ei[e]; dst = ei[EE_ + e]; }
    else         { src = e - EE_; dst = e - EE_; }
    int pos = g_off[dst] + atomicAdd(&g_wpos[dst], 1);
    g_srcs[pos] = src;
}

// ---------------- SGEMM NN: C[M,Nn] = A[M,K] @ B[K,Nn] ---------------------
#define BM 128
#define BN 128
#define BK 8
__global__ __launch_bounds__(256) void sgemm_nn(
    const float* __restrict__ A, const float* __restrict__ B,
    float* __restrict__ C, int M, int Nn, int K)
{
    __shared__ float As[BK][BM];
    __shared__ float Bs[BK][BN];
    int m0 = blockIdx.y * BM, n0 = blockIdx.x * BN;
    int tid = threadIdx.x;
    int rm = (tid / 16) * 8, rn = (tid % 16) * 8;
    float acc[8][8];
#pragma unroll
    for (int i = 0; i < 8; i++)
#pragma unroll
        for (int j = 0; j < 8; j++) acc[i][j] = 0.f;

    for (int k0 = 0; k0 < K; k0 += BK) {
#pragma unroll
        for (int i = tid; i < BM * BK; i += 256) {
            int r = i / BK, c = i % BK;
            int gm = m0 + r;
            As[c][r] = (gm < M) ? A[(size_t)gm * K + k0 + c] : 0.f;
        }
#pragma unroll
        for (int i = tid; i < BK * BN; i += 256) {
            int r = i / BN, c = i % BN;
            int gn = n0 + c;
            Bs[r][c] = (gn < Nn) ? B[(size_t)(k0 + r) * Nn + gn] : 0.f;
        }
        __syncthreads();
#pragma unroll
        for (int kk = 0; kk < BK; kk++) {
            float a[8], b[8];
#pragma unroll
            for (int i = 0; i < 8; i++) a[i] = As[kk][rm + i];
#pragma unroll
            for (int j = 0; j < 8; j++) b[j] = Bs[kk][rn + j];
#pragma unroll
            for (int i = 0; i < 8; i++)
#pragma unroll
                for (int j = 0; j < 8; j++) acc[i][j] += a[i] * b[j];
        }
        __syncthreads();
    }
#pragma unroll
    for (int i = 0; i < 8; i++) {
        int gm = m0 + rm + i;
        if (gm >= M) continue;
#pragma unroll
        for (int j = 0; j < 8; j++) {
            int gn = n0 + rn + j;
            if (gn < Nn) C[(size_t)gm * Nn + gn] = acc[i][j];
        }
    }
}

// ---------------- attention logits per (node, head) ------------------------
__global__ void attn_kernel(const float* __restrict__ a_src,
                            const float* __restrict__ a_dst)
{
    int n = blockIdx.x;
    int w = threadIdx.x / 32;      // head
    int lane = threadIdx.x % 32;
    const float* hp = &g_h[(size_t)n * HF_ + w * F_];
    float ss = 0.f, sd = 0.f;
#pragma unroll
    for (int f = lane; f < F_; f += 32) {
        float hv = hp[f];
        ss += hv * a_src[w * F_ + f];
        sd += hv * a_dst[w * F_ + f];
    }
#pragma unroll
    for (int o = 16; o; o >>= 1) {
        ss += __shfl_down_sync(0xffffffffu, ss, o);
        sd += __shfl_down_sync(0xffffffffu, sd, o);
    }
    if (lane == 0) {
        g_als[n * H_ + w] = ss;
        g_ald[n * H_ + w] = sd;
    }
}

// ---------------- per-dst segment softmax + aggregation --------------------
__device__ __forceinline__ float leaky(float x) {
    return x > 0.f ? x : LEAKY * x;
}

__global__ __launch_bounds__(256) void aggregate(
    const float* __restrict__ bias, float* __restrict__ xout, int mode /*0 relu,1 tanh*/)
{
    __shared__ float red[256];
    __shared__ float sm[H_], ssum[H_];
    __shared__ float alpha_sh[CH][H_];
    __shared__ int   src_sh[CH];

    int n = blockIdx.x, tid = threadIdx.x;
    int beg = g_off[n];
    int deg = g_off[n + 1] - beg;

    float ald[H_];
#pragma unroll
    for (int h = 0; h < H_; h++) ald[h] = g_ald[n * H_ + h];

    // pass 1: per-head max
    float mloc[H_];
#pragma unroll
    for (int h = 0; h < H_; h++) mloc[h] = -1e30f;
    for (int i = tid; i < deg; i += 256) {
        int s = g_srcs[beg + i];
#pragma unroll
        for (int h = 0; h < H_; h++) {
            float e = leaky(g_als[s * H_ + h] + ald[h]);
            mloc[h] = fmaxf(mloc[h], e);
        }
    }
#pragma unroll
    for (int h = 0; h < H_; h++) {
        red[tid] = mloc[h];
        __syncthreads();
        for (int o = 128; o; o >>= 1) {
            if (tid < o) red[tid] = fmaxf(red[tid], red[tid + o]);
            __syncthreads();
        }
        if (tid == 0) sm[h] = red[0];
        __syncthreads();
    }

    // pass 2: per-head exp-sum
    float sloc[H_] = {0.f, 0.f, 0.f, 0.f};
    for (int i = tid; i < deg; i += 256) {
        int s = g_srcs[beg + i];
#pragma unroll
        for (int h = 0; h < H_; h++) {
            float e = leaky(g_als[s * H_ + h] + ald[h]);
            sloc[h] += expf(e - sm[h]);
        }
    }
#pragma unroll
    for (int h = 0; h < H_; h++) {
        red[tid] = sloc[h];
        __syncthreads();
        for (int o = 128; o; o >>= 1) {
            if (tid < o) red[tid] += red[tid + o];
            __syncthreads();
        }
        if (tid == 0) ssum[h] = red[0];
        __syncthreads();
    }

    // pass 3: chunked alpha + weighted aggregation
    float acc[H_] = {0.f, 0.f, 0.f, 0.f};
    for (int base = 0; base < deg; base += CH) {
        int c = min(CH, deg - base);
        __syncthreads();
        for (int i = tid; i < c; i += 256) {
            int s = g_srcs[beg + base + i];
            src_sh[i] = s;
#pragma unroll
            for (int h = 0; h < H_; h++) {
                float e = leaky(g_als[s * H_ + h] + ald[h]);
                alpha_sh[i][h] = expf(e - sm[h]) / (ssum[h] + 1e-16f);
            }
        }
        __syncthreads();
        for (int j = 0; j < c; j++) {
            int s = src_sh[j];
            const float* hp = &g_h[(size_t)s * HF_ + tid];
            float a0 = alpha_sh[j][0], a1 = alpha_sh[j][1];
            float a2 = alpha_sh[j][2], a3 = alpha_sh[j][3];
            acc[0] += a0 * hp[0 * F_];
            acc[1] += a1 * hp[1 * F_];
            acc[2] += a2 * hp[2 * F_];
            acc[3] += a3 * hp[3 * F_];
        }
    }

    float v = (acc[0] + acc[1] + acc[2] + acc[3]) * 0.25f + bias[tid];
    v = mode ? tanhf(v) : fmaxf(v, 0.f);
    xout[(size_t)n * F_ + tid] = v;
}

// ---------------- z split into bf16 hi/lo -----------------------------------
__global__ void zsplit(const float* __restrict__ z) {
    int i = blockIdx.x * blockDim.x + threadIdx.x;
    if (i >= NN_ * F_) return;
    float v = z[i];
    __nv_bfloat16 h = __float2bfloat16(v);
    g_zh[i] = h;
    g_zl[i] = __float2bfloat16(v - __bfloat162float(h));
}

// ---------------- adj = sigmoid(z @ z^T) via mma.sync bf16 split ------------
// CTA: 128x128 output tile, 8 warps (2 m x 4 n), each warp 64x32.
// K_eff = 768 (3 segments x 256: hi*hi, hi*lo, lo*hi), chunks of 32,
// each chunk stored as 2 sub-tiles [128][16] bf16, double-buffered.

__device__ __forceinline__ void mma16816(float c[4], uint32_t a0, uint32_t a1,
                                         uint32_t a2, uint32_t a3,
                                         uint32_t b0, uint32_t b1) {
    asm volatile(
        "mma.sync.aligned.m16n8k16.row.col.f32.bf16.bf16.f32 "
        "{%0,%1,%2,%3}, {%4,%5,%6,%7}, {%8,%9}, {%0,%1,%2,%3};"
        : "+f"(c[0]), "+f"(c[1]), "+f"(c[2]), "+f"(c[3])
        : "r"(a0), "r"(a1), "r"(a2), "r"(a3), "r"(b0), "r"(b1));
}

#define NCHUNK 24   // 768 / 32

__global__ __launch_bounds__(256, 1) void adj_hmma(float* __restrict__ out)
{
    // [buf][sub][row][16] bf16
    __shared__ __align__(16) __nv_bfloat16 sA[2][2][128][16];
    __shared__ __align__(16) __nv_bfloat16 sB[2][2][128][16];

    int tid = threadIdx.x;
    int wid = tid >> 5, lane = tid & 31;
    int wm = wid >> 2, wn = wid & 3;         // warp tile: rows wm*64, cols wn*32
    int g = lane >> 2, t = lane & 3;
    int m0 = blockIdx.y * 128, n0 = blockIdx.x * 128;

    const __nv_bfloat16* Aseg[3] = { g_zh, g_zh, g_zl };
    const __nv_bfloat16* Bseg[3] = { g_zh, g_zl, g_zh };

    float acc[4][4][4];
#pragma unroll
    for (int i = 0; i < 4; i++)
#pragma unroll
        for (int j = 0; j < 4; j++)
#pragma unroll
            for (int k = 0; k < 4; k++) acc[i][j][k] = 0.f;

    // loader: thread handles sub s = tid>>7, row r = tid&127; 32B per tile
    int ls = tid >> 7, lr = tid & 127;

    uint4 ra0, ra1, rb0, rb1;
    auto load_chunk = [&](int c) {
        int seg = c / 8;
        int kk = (c % 8) * 32 + ls * 16;
        const __nv_bfloat16* As = Aseg[seg];
        const __nv_bfloat16* Bs = Bseg[seg];
        ra0 = make_uint4(0, 0, 0, 0); ra1 = ra0; rb0 = ra0; rb1 = ra0;
        int gm = m0 + lr, gn = n0 + lr;
        if (gm < NN_) {
            const uint4* p = reinterpret_cast<const uint4*>(As + (size_t)gm * F_ + kk);
            ra0 = p[0]; ra1 = p[1];
        }
        if (gn < NN_) {
            const uint4* p = reinterpret_cast<const uint4*>(Bs + (size_t)gn * F_ + kk);
            rb0 = p[0]; rb1 = p[1];
        }
    };
    auto store_chunk = [&](int buf) {
        uint4* pa = reinterpret_cast<uint4*>(&sA[buf][ls][lr][0]);
        pa[0] = ra0; pa[1] = ra1;
        uint4* pb = reinterpret_cast<uint4*>(&sB[buf][ls][lr][0]);
        pb[0] = rb0; pb[1] = rb1;
    };

    load_chunk(0);
    store_chunk(0);
    __syncthreads();

    for (int c = 0; c < NCHUNK; c++) {
        int buf = c & 1;
        if (c + 1 < NCHUNK) load_chunk(c + 1);

#pragma unroll
        for (int s = 0; s < 2; s++) {
            const uint32_t* Aw = reinterpret_cast<const uint32_t*>(&sA[buf][s][0][0]);
            const uint32_t* Bw = reinterpret_cast<const uint32_t*>(&sB[buf][s][0][0]);
            uint32_t af[4][4], bf[4][2];
#pragma unroll
            for (int mt = 0; mt < 4; mt++) {
                int r = wm * 64 + mt * 16 + g;
                af[mt][0] = Aw[r * 8 + t];
                af[mt][1] = Aw[(r + 8) * 8 + t];
                af[mt][2] = Aw[r * 8 + t + 4];
                af[mt][3] = Aw[(r + 8) * 8 + t + 4];
            }
#pragma unroll
            for (int nt = 0; nt < 4; nt++) {
                int r = wn * 32 + nt * 8 + g;
                bf[nt][0] = Bw[r * 8 + t];
                bf[nt][1] = Bw[r * 8 + t + 4];
            }
#pragma unroll
            for (int mt = 0; mt < 4; mt++)
#pragma unroll
                for (int nt = 0; nt < 4; nt++)
                    mma16816(acc[mt][nt], af[mt][0], af[mt][1], af[mt][2], af[mt][3],
                             bf[nt][0], bf[nt][1]);
        }

        if (c + 1 < NCHUNK) {
            __syncthreads();
            store_chunk((c + 1) & 1);
            __syncthreads();
        }
    }

    // epilogue: fused sigmoid, float2 stores
#pragma unroll
    for (int mt = 0; mt < 4; mt++) {
        int gm = m0 + wm * 64 + mt * 16 + g;
#pragma unroll
        for (int nt = 0; nt < 4; nt++) {
            int gn = n0 + wn * 32 + nt * 8 + 2 * t;
            if (gn >= NN_) continue;
            float* p0 = out + (size_t)gm * NN_ + gn;
            if (gm < NN_) {
                float2 v;
                v.x = 1.f / (1.f + __expf(-acc[mt][nt][0]));
                v.y = 1.f / (1.f + __expf(-acc[mt][nt][1]));
                *reinterpret_cast<float2*>(p0) = v;
            }
            if (gm + 8 < NN_) {
                float2 v;
                v.x = 1.f / (1.f + __expf(-acc[mt][nt][2]));
                v.y = 1.f / (1.f + __expf(-acc[mt][nt][3]));
                *reinterpret_cast<float2*>(p0 + (size_t)8 * NN_) = v;
            }
        }
    }
}

// ---------------- driver ----------------------------------------------------
extern "C" void kernel_launch(void* const* d_in, const int* in_sizes, int n_in,
                              void* d_out, int out_size)
{
    const float* x  = (const float*)d_in[0];
    const int*   ei = (const int*)d_in[1];
    const float* W[4];  const float* as_[4]; const float* ad_[4]; const float* b_[4];
    for (int l = 0; l < 4; l++) {
        W[l]   = (const float*)d_in[2 + 4 * l];
        as_[l] = (const float*)d_in[3 + 4 * l];
        ad_[l] = (const float*)d_in[4 + 4 * l];
        b_[l]  = (const float*)d_in[5 + 4 * l];
    }
    float* out = (float*)d_out;

    float *p_h, *p_act0, *p_act1, *p_z;
    cudaGetSymbolAddress((void**)&p_h,    g_h);
    cudaGetSymbolAddress((void**)&p_act0, g_act0);
    cudaGetSymbolAddress((void**)&p_act1, g_act1);
    cudaGetSymbolAddress((void**)&p_z,    g_zbuf);

    const size_t ADJ = (size_t)NN_ * NN_;
    bool z_in_out = ((size_t)out_size >= ADJ + (size_t)NN_ * F_);
    float* zptr = z_in_out ? (out + ADJ) : p_z;

    // ---- CSR build ----
    zero_int2<<<(NN_ + 255) / 256, 256>>>();
    count_kernel<<<(ETOT + 255) / 256, 256>>>(ei);
    scan_kernel<<<1, 1024>>>();
    scatter_kernel<<<(ETOT + 255) / 256, 256>>>(ei);

    // ---- 4 GAT layers ----
    const float* xin = x;
    float* xouts[4] = {p_act0, p_act1, p_act0, zptr};
    dim3 ggrid((HF_ + BN - 1) / BN, (NN_ + BM - 1) / BM);
    for (int l = 0; l < 4; l++) {
        sgemm_nn<<<ggrid, 256>>>(xin, W[l], p_h, NN_, HF_, F_);
        attn_kernel<<<NN_, H_ * 32>>>(as_[l], ad_[l]);
        aggregate<<<NN_, 256>>>(b_[l], xouts[l], (l == 3) ? 1 : 0);
        xin = xouts[l];
    }

    // ---- adj_recon = sigmoid(z @ z^T) via HMMA bf16 split ----
    zsplit<<<(NN_ * F_ + 255) / 256, 256>>>(zptr);
    dim3 fgrid((NN_ + 127) / 128, (NN_ + 127) / 128);
    adj_hmma<<<fgrid, 256>>>(out);
}

// round 4
// speedup vs baseline: 2.4067x; 2.0735x over previous
#include <cuda_runtime.h>
#include <cuda_bf16.h>
#include <math.h>
#include <stdint.h>

#define NN_   10000
#define EE_   320000
#define ETOT  (EE_ + NN_)
#define H_    4
#define F_    256
#define HF_   1024
#define LEAKY 0.2f
#define CH    512

// ---------------- scratch (device globals) ----------------------------------
__device__ float g_h[(size_t)NN_ * HF_];
__device__ float g_als[NN_ * H_];
__device__ float g_ald[NN_ * H_];
__device__ float g_act0[(size_t)NN_ * F_];
__device__ float g_zbuf[(size_t)NN_ * F_];
__device__ int   g_cnt[NN_];
__device__ int   g_off[NN_ + 1];
__device__ int   g_wpos[NN_];
__device__ int   g_srcs[ETOT];
__device__ __align__(16) __nv_bfloat16 g_bfh[(size_t)NN_ * F_];  // activation hi
__device__ __align__(16) __nv_bfloat16 g_bfl[(size_t)NN_ * F_];  // activation lo
__device__ __align__(16) __nv_bfloat16 g_wth[(size_t)HF_ * F_];  // W^T hi [1024][256]
__device__ __align__(16) __nv_bfloat16 g_wtl[(size_t)HF_ * F_];  // W^T lo

// ---------------- small PTX helpers -----------------------------------------
__device__ __forceinline__ uint32_t smem_u32(const void* p) {
    uint32_t a;
    asm("{ .reg .u64 t; cvta.to.shared.u64 t, %1; cvt.u32.u64 %0, t; }" : "=r"(a) : "l"(p));
    return a;
}
__device__ __forceinline__ void cp16(uint32_t dst, const void* src, bool valid) {
    int sz = valid ? 16 : 0;
    asm volatile("cp.async.cg.shared.global [%0], [%1], 16, %2;"
                 :: "r"(dst), "l"(src), "r"(sz) : "memory");
}
__device__ __forceinline__ void cp_commit() {
    asm volatile("cp.async.commit_group;" ::: "memory");
}
__device__ __forceinline__ void cp_wait0() {
    asm volatile("cp.async.wait_group 0;" ::: "memory");
}
__device__ __forceinline__ void ldsm4(uint32_t& r0, uint32_t& r1, uint32_t& r2,
                                      uint32_t& r3, uint32_t a) {
    asm volatile("ldmatrix.sync.aligned.m8n8.x4.shared.b16 {%0,%1,%2,%3}, [%4];"
                 : "=r"(r0), "=r"(r1), "=r"(r2), "=r"(r3) : "r"(a));
}
__device__ __forceinline__ void mma16816(float c[4], uint32_t a0, uint32_t a1,
                                         uint32_t a2, uint32_t a3,
                                         uint32_t b0, uint32_t b1) {
    asm volatile(
        "mma.sync.aligned.m16n8k16.row.col.f32.bf16.bf16.f32 "
        "{%0,%1,%2,%3}, {%4,%5,%6,%7}, {%8,%9}, {%0,%1,%2,%3};"
        : "+f"(c[0]), "+f"(c[1]), "+f"(c[2]), "+f"(c[3])
        : "r"(a0), "r"(a1), "r"(a2), "r"(a3), "r"(b0), "r"(b1));
}

// ---------------- CSR build -------------------------------------------------
__global__ void zero_int2() {
    int i = blockIdx.x * blockDim.x + threadIdx.x;
    if (i < NN_) { g_cnt[i] = 0; g_wpos[i] = 0; }
}
__global__ void count_kernel(const int* __restrict__ ei) {
    int e = blockIdx.x * blockDim.x + threadIdx.x;
    if (e >= ETOT) return;
    int dst = (e < EE_) ? ei[EE_ + e] : (e - EE_);
    atomicAdd(&g_cnt[dst], 1);
}
__global__ void scan_kernel() {
    __shared__ int sh[1024];
    int tid = threadIdx.x;
    int carry = 0;
    for (int base = 0; base < NN_; base += 1024) {
        int v = (base + tid < NN_) ? g_cnt[base + tid] : 0;
        sh[tid] = v;
        __syncthreads();
        for (int d = 1; d < 1024; d <<= 1) {
            int t = (tid >= d) ? sh[tid - d] : 0;
            __syncthreads();
            sh[tid] += t;
            __syncthreads();
        }
        if (base + tid < NN_) g_off[base + tid] = carry + sh[tid] - v;
        int tot = sh[1023];
        __syncthreads();
        carry += tot;
    }
    if (tid == 0) g_off[NN_] = carry;
}
__global__ void scatter_kernel(const int* __restrict__ ei) {
    int e = blockIdx.x * blockDim.x + threadIdx.x;
    if (e >= ETOT) return;
    int src, dst;
    if (e < EE_) { src = ei[e]; dst = ei[EE_ + e]; }
    else         { src = e - EE_; dst = e - EE_; }
    int pos = g_off[dst] + atomicAdd(&g_wpos[dst], 1);
    g_srcs[pos] = src;
}

// ---------------- unified bf16-split HMMA GEMM ------------------------------
// C[M, Ncols] = A[M,256] @ B[Ncols,256]^T, A/B given as bf16 hi+lo (3 segments).
// CTA = 128x128 tile, 8 warps (2x4), warp 64x32. K chunks of 64, double-buffered
// cp.async, SW-swizzled smem, ldmatrix.x4 fragments.
// mode 0: store fp32. mode 1: sigmoid. ldc = row stride of C.

#define GBUF 32768   // bytes per (A+B) buffer: 2 x 128 rows x 128B

__global__ __launch_bounds__(256) void hmma_tt(
    const __nv_bfloat16* __restrict__ Ah, const __nv_bfloat16* __restrict__ Al,
    const __nv_bfloat16* __restrict__ Bh, const __nv_bfloat16* __restrict__ Bl,
    float* __restrict__ C, int M, int Ncols, size_t ldc, int mode)
{
    extern __shared__ char dyn_smem[];
    uint32_t smem_base = smem_u32(dyn_smem);

    int tid = threadIdx.x;
    int wid = tid >> 5, lane = tid & 31;
    int wm = wid >> 2, wn = wid & 3;
    int g = lane >> 2, t = lane & 3;
    int m0 = blockIdx.y * 128, n0 = blockIdx.x * 128;

    const __nv_bfloat16* segA[3] = { Ah, Ah, Al };
    const __nv_bfloat16* segB[3] = { Bh, Bl, Bh };

    float acc[4][4][4];
#pragma unroll
    for (int i = 0; i < 4; i++)
#pragma unroll
        for (int j = 0; j < 4; j++)
#pragma unroll
            for (int k = 0; k < 4; k++) acc[i][j][k] = 0.f;

    auto issue_chunk = [&](int c, int buf) {
        int seg = c >> 2, k0 = (c & 3) * 64;
        const __nv_bfloat16* As = segA[seg];
        const __nv_bfloat16* Bs = segB[seg];
        uint32_t sa = smem_base + buf * GBUF;
        uint32_t sb = sa + 16384;
#pragma unroll
        for (int i = 0; i < 4; i++) {
            int idx = tid + i * 256;
            int r = idx >> 3, s16 = idx & 7;
            uint32_t off = (uint32_t)(r * 128 + ((s16 ^ (r & 7)) << 4));
            int gm = m0 + r;
            bool va = gm < M;
            cp16(sa + off, As + ((size_t)(va ? gm : 0) * F_ + k0 + s16 * 8), va);
            int gn = n0 + r;
            bool vb = gn < Ncols;
            cp16(sb + off, Bs + ((size_t)(vb ? gn : 0) * F_ + k0 + s16 * 8), vb);
        }
        cp_commit();
    };

    issue_chunk(0, 0);

    int lr = lane & 15;
    for (int c = 0; c < 12; c++) {
        cp_wait0();
        __syncthreads();
        if (c < 11) issue_chunk(c + 1, (c + 1) & 1);

        uint32_t sa = smem_base + (c & 1) * GBUF;
        uint32_t sb = sa + 16384;
#pragma unroll
        for (int ks = 0; ks < 4; ks++) {
            int lseg = 2 * ks + (lane >> 4);
            uint32_t af[4][4];
#pragma unroll
            for (int mt = 0; mt < 4; mt++) {
                int row = wm * 64 + mt * 16 + lr;
                uint32_t addr = sa + row * 128 + ((uint32_t)(lseg ^ (row & 7)) << 4);
                ldsm4(af[mt][0], af[mt][1], af[mt][2], af[mt][3], addr);
            }
            uint32_t bq[2][4];
#pragma unroll
            for (int hb = 0; hb < 2; hb++) {
                int row = wn * 32 + hb * 16 + lr;
                uint32_t addr = sb + row * 128 + ((uint32_t)(lseg ^ (row & 7)) << 4);
                ldsm4(bq[hb][0], bq[hb][1], bq[hb][2], bq[hb][3], addr);
            }
#pragma unroll
            for (int mt = 0; mt < 4; mt++)
#pragma unroll
                for (int nt = 0; nt < 4; nt++)
                    mma16816(acc[mt][nt],
                             af[mt][0], af[mt][1], af[mt][2], af[mt][3],
                             bq[nt >> 1][nt & 1], bq[nt >> 1][(nt & 1) + 2]);
        }
    }

    // epilogue
#pragma unroll
    for (int mt = 0; mt < 4; mt++) {
        int gm = m0 + wm * 64 + mt * 16 + g;
#pragma unroll
        for (int nt = 0; nt < 4; nt++) {
            int gn = n0 + wn * 32 + nt * 8 + 2 * t;
            if (gn >= Ncols) continue;
            float* p0 = C + (size_t)gm * ldc + gn;
            if (mode == 0) {
                if (gm < M) {
                    float2 v = make_float2(acc[mt][nt][0], acc[mt][nt][1]);
                    *reinterpret_cast<float2*>(p0) = v;
                }
                if (gm + 8 < M) {
                    float2 v = make_float2(acc[mt][nt][2], acc[mt][nt][3]);
                    *reinterpret_cast<float2*>(p0 + 8 * ldc) = v;
                }
            } else {
                if (gm < M) {
                    float2 v;
                    v.x = 1.f / (1.f + __expf(-acc[mt][nt][0]));
                    v.y = 1.f / (1.f + __expf(-acc[mt][nt][1]));
                    *reinterpret_cast<float2*>(p0) = v;
                }
                if (gm + 8 < M) {
                    float2 v;
                    v.x = 1.f / (1.f + __expf(-acc[mt][nt][2]));
                    v.y = 1.f / (1.f + __expf(-acc[mt][nt][3]));
                    *reinterpret_cast<float2*>(p0 + 8 * ldc) = v;
                }
            }
        }
    }
}

// ---------------- W transpose + hi/lo split ---------------------------------
// W[k=256][n=1024] fp32 -> g_wth/g_wtl [n][256] bf16
__global__ void wt_split(const float* __restrict__ W) {
    __shared__ float tbuf[32][33];
    int bx = blockIdx.x, by = blockIdx.y;      // n-tile, k-tile
    int x = threadIdx.x, y = threadIdx.y;      // 32 x 8
    for (int i = y; i < 32; i += 8)
        tbuf[i][x] = W[(size_t)(by * 32 + i) * HF_ + bx * 32 + x];
    __syncthreads();
    for (int i = y; i < 32; i += 8) {
        float v = tbuf[x][i];
        __nv_bfloat16 h = __float2bfloat16(v);
        size_t o = (size_t)(bx * 32 + i) * F_ + by * 32 + x;
        g_wth[o] = h;
        g_wtl[o] = __float2bfloat16(v - __bfloat162float(h));
    }
}

// ---------------- x -> bf16 hi/lo (layer 0 input) ---------------------------
__global__ void split_x(const float* __restrict__ x) {
    int i = blockIdx.x * blockDim.x + threadIdx.x;
    if (i >= NN_ * F_) return;
    float v = x[i];
    __nv_bfloat16 h = __float2bfloat16(v);
    g_bfh[i] = h;
    g_bfl[i] = __float2bfloat16(v - __bfloat162float(h));
}

// ---------------- attention logits ------------------------------------------
__global__ void attn_kernel(const float* __restrict__ a_src,
                            const float* __restrict__ a_dst)
{
    int n = blockIdx.x;
    int w = threadIdx.x / 32;
    int lane = threadIdx.x % 32;
    const float* hp = &g_h[(size_t)n * HF_ + w * F_];
    float ss = 0.f, sd = 0.f;
#pragma unroll
    for (int f = lane; f < F_; f += 32) {
        float hv = hp[f];
        ss += hv * a_src[w * F_ + f];
        sd += hv * a_dst[w * F_ + f];
    }
#pragma unroll
    for (int o = 16; o; o >>= 1) {
        ss += __shfl_down_sync(0xffffffffu, ss, o);
        sd += __shfl_down_sync(0xffffffffu, sd, o);
    }
    if (lane == 0) {
        g_als[n * H_ + w] = ss;
        g_ald[n * H_ + w] = sd;
    }
}

// ---------------- per-dst softmax + aggregation (+ bf16 split out) ----------
__device__ __forceinline__ float leaky(float x) {
    return x > 0.f ? x : LEAKY * x;
}

__global__ __launch_bounds__(256) void aggregate(
    const float* __restrict__ bias, float* __restrict__ xout, int mode)
{
    __shared__ float red[256];
    __shared__ float sm[H_], ssum[H_];
    __shared__ float alpha_sh[CH][H_];
    __shared__ int   src_sh[CH];

    int n = blockIdx.x, tid = threadIdx.x;
    int beg = g_off[n];
    int deg = g_off[n + 1] - beg;

    float ald[H_];
#pragma unroll
    for (int h = 0; h < H_; h++) ald[h] = g_ald[n * H_ + h];

    float mloc[H_];
#pragma unroll
    for (int h = 0; h < H_; h++) mloc[h] = -1e30f;
    for (int i = tid; i < deg; i += 256) {
        int s = g_srcs[beg + i];
#pragma unroll
        for (int h = 0; h < H_; h++) {
            float e = leaky(g_als[s * H_ + h] + ald[h]);
            mloc[h] = fmaxf(mloc[h], e);
        }
    }
#pragma unroll
    for (int h = 0; h < H_; h++) {
        red[tid] = mloc[h];
        __syncthreads();
        for (int o = 128; o; o >>= 1) {
            if (tid < o) red[tid] = fmaxf(red[tid], red[tid + o]);
            __syncthreads();
        }
        if (tid == 0) sm[h] = red[0];
        __syncthreads();
    }

    float sloc[H_] = {0.f, 0.f, 0.f, 0.f};
    for (int i = tid; i < deg; i += 256) {
        int s = g_srcs[beg + i];
#pragma unroll
        for (int h = 0; h < H_; h++) {
            float e = leaky(g_als[s * H_ + h] + ald[h]);
            sloc[h] += expf(e - sm[h]);
        }
    }
#pragma unroll
    for (int h = 0; h < H_; h++) {
        red[tid] = sloc[h];
        __syncthreads();
        for (int o = 128; o; o >>= 1) {
            if (tid < o) red[tid] += red[tid + o];
            __syncthreads();
        }
        if (tid == 0) ssum[h] = red[0];
        __syncthreads();
    }

    float acc[H_] = {0.f, 0.f, 0.f, 0.f};
    for (int base = 0; base < deg; base += CH) {
        int c = min(CH, deg - base);
        __syncthreads();
        for (int i = tid; i < c; i += 256) {
            int s = g_srcs[beg + base + i];
            src_sh[i] = s;
#pragma unroll
            for (int h = 0; h < H_; h++) {
                float e = leaky(g_als[s * H_ + h] + ald[h]);
                alpha_sh[i][h] = expf(e - sm[h]) / (ssum[h] + 1e-16f);
            }
        }
        __syncthreads();
        for (int j = 0; j < c; j++) {
            int s = src_sh[j];
            const float* hp = &g_h[(size_t)s * HF_ + tid];
            float a0 = alpha_sh[j][0], a1 = alpha_sh[j][1];
            float a2 = alpha_sh[j][2], a3 = alpha_sh[j][3];
            acc[0] += a0 * hp[0 * F_];
            acc[1] += a1 * hp[1 * F_];
            acc[2] += a2 * hp[2 * F_];
            acc[3] += a3 * hp[3 * F_];
        }
    }

    float v = (acc[0] + acc[1] + acc[2] + acc[3]) * 0.25f + bias[tid];
    v = mode ? tanhf(v) : fmaxf(v, 0.f);
    size_t o = (size_t)n * F_ + tid;
    xout[o] = v;
    __nv_bfloat16 hh = __float2bfloat16(v);
    g_bfh[o] = hh;
    g_bfl[o] = __float2bfloat16(v - __bfloat162float(hh));
}

// ---------------- driver ----------------------------------------------------
extern "C" void kernel_launch(void* const* d_in, const int* in_sizes, int n_in,
                              void* d_out, int out_size)
{
    const float* x  = (const float*)d_in[0];
    const int*   ei = (const int*)d_in[1];
    const float* W[4];  const float* as_[4]; const float* ad_[4]; const float* b_[4];
    for (int l = 0; l < 4; l++) {
        W[l]   = (const float*)d_in[2 + 4 * l];
        as_[l] = (const float*)d_in[3 + 4 * l];
        ad_[l] = (const float*)d_in[4 + 4 * l];
        b_[l]  = (const float*)d_in[5 + 4 * l];
    }
    float* out = (float*)d_out;

    float *p_h, *p_act0, *p_z;
    __nv_bfloat16 *p_bfh, *p_bfl, *p_wth, *p_wtl;
    cudaGetSymbolAddress((void**)&p_h,    g_h);
    cudaGetSymbolAddress((void**)&p_act0, g_act0);
    cudaGetSymbolAddress((void**)&p_z,    g_zbuf);
    cudaGetSymbolAddress((void**)&p_bfh,  g_bfh);
    cudaGetSymbolAddress((void**)&p_bfl,  g_bfl);
    cudaGetSymbolAddress((void**)&p_wth,  g_wth);
    cudaGetSymbolAddress((void**)&p_wtl,  g_wtl);

    const size_t ADJ = (size_t)NN_ * NN_;
    bool z_in_out = ((size_t)out_size >= ADJ + (size_t)NN_ * F_);
    float* zptr = z_in_out ? (out + ADJ) : p_z;

    static bool smem_attr = false;
    if (!smem_attr) {
        cudaFuncSetAttribute(hmma_tt, cudaFuncAttributeMaxDynamicSharedMemorySize,
                             2 * GBUF);
        smem_attr = true;
    }

    // ---- CSR build ----
    zero_int2<<<(NN_ + 255) / 256, 256>>>();
    count_kernel<<<(ETOT + 255) / 256, 256>>>(ei);
    scan_kernel<<<1, 1024>>>();
    scatter_kernel<<<(ETOT + 255) / 256, 256>>>(ei);

    // ---- 4 GAT layers ----
    split_x<<<(NN_ * F_ + 255) / 256, 256>>>(x);
    dim3 lgrid(HF_ / 128, (NN_ + 127) / 128);
    for (int l = 0; l < 4; l++) {
        wt_split<<<dim3(32, 8), dim3(32, 8)>>>(W[l]);
        hmma_tt<<<lgrid, 256, 2 * GBUF>>>(p_bfh, p_bfl, p_wth, p_wtl,
                                          p_h, NN_, HF_, HF_, 0);
        attn_kernel<<<NN_, H_ * 32>>>(as_[l], ad_[l]);
        aggregate<<<NN_, 256>>>(b_[l], (l == 3) ? zptr : p_act0, (l == 3) ? 1 : 0);
    }

    // ---- adj_recon = sigmoid(z @ z^T) ----
    dim3 fgrid((NN_ + 127) / 128, (NN_ + 127) / 128);
    hmma_tt<<<fgrid, 256, 2 * GBUF>>>(p_bfh, p_bfl, p_bfh, p_bfl,
                                      out, NN_, NN_, NN_, 1);
}

// round 5
// speedup vs baseline: 2.8118x; 1.1684x over previous
#include <cuda_runtime.h>
#include <cuda_bf16.h>
#include <math.h>
#include <stdint.h>

#define NN_   10000
#define EE_   320000
#define ETOT  (EE_ + NN_)
#define H_    4
#define F_    256
#define HF_   1024
#define LEAKY 0.2f
#define CH    512

// ---------------- scratch (device globals) ----------------------------------
__device__ float g_h[(size_t)NN_ * HF_];
__device__ float g_als[NN_ * H_];
__device__ float g_ald[NN_ * H_];
__device__ float g_act0[(size_t)NN_ * F_];
__device__ float g_zbuf[(size_t)NN_ * F_];
__device__ int   g_cnt[NN_];
__device__ int   g_off[NN_ + 1];
__device__ int   g_wpos[NN_];
__device__ int   g_srcs[ETOT];
__device__ __align__(16) __nv_bfloat16 g_bfh[(size_t)NN_ * F_];  // activation hi
__device__ __align__(16) __nv_bfloat16 g_bfl[(size_t)NN_ * F_];  // activation lo
__device__ __align__(16) __nv_bfloat16 g_wth[(size_t)HF_ * F_];  // W^T hi [1024][256]
__device__ __align__(16) __nv_bfloat16 g_wtl[(size_t)HF_ * F_];  // W^T lo

// ---------------- small PTX helpers -----------------------------------------
__device__ __forceinline__ uint32_t smem_u32(const void* p) {
    uint32_t a;
    asm("{ .reg .u64 t; cvta.to.shared.u64 t, %1; cvt.u32.u64 %0, t; }" : "=r"(a) : "l"(p));
    return a;
}
__device__ __forceinline__ void cp16(uint32_t dst, const void* src, bool valid) {
    int sz = valid ? 16 : 0;
    asm volatile("cp.async.cg.shared.global [%0], [%1], 16, %2;"
                 :: "r"(dst), "l"(src), "r"(sz) : "memory");
}
__device__ __forceinline__ void cp_commit() {
    asm volatile("cp.async.commit_group;" ::: "memory");
}
__device__ __forceinline__ void cp_wait0() {
    asm volatile("cp.async.wait_group 0;" ::: "memory");
}
__device__ __forceinline__ void ldsm4(uint32_t& r0, uint32_t& r1, uint32_t& r2,
                                      uint32_t& r3, uint32_t a) {
    asm volatile("ldmatrix.sync.aligned.m8n8.x4.shared.b16 {%0,%1,%2,%3}, [%4];"
                 : "=r"(r0), "=r"(r1), "=r"(r2), "=r"(r3) : "r"(a));
}
__device__ __forceinline__ void mma16816(float c[4], uint32_t a0, uint32_t a1,
                                         uint32_t a2, uint32_t a3,
                                         uint32_t b0, uint32_t b1) {
    asm volatile(
        "mma.sync.aligned.m16n8k16.row.col.f32.bf16.bf16.f32 "
        "{%0,%1,%2,%3}, {%4,%5,%6,%7}, {%8,%9}, {%0,%1,%2,%3};"
        : "+f"(c[0]), "+f"(c[1]), "+f"(c[2]), "+f"(c[3])
        : "r"(a0), "r"(a1), "r"(a2), "r"(a3), "r"(b0), "r"(b1));
}

// ---------------- CSR build -------------------------------------------------
__global__ void zero_int2() {
    int i = blockIdx.x * blockDim.x + threadIdx.x;
    if (i < NN_) { g_cnt[i] = 0; g_wpos[i] = 0; }
}
__global__ void count_kernel(const int* __restrict__ ei) {
    int e = blockIdx.x * blockDim.x + threadIdx.x;
    if (e >= ETOT) return;
    int dst = (e < EE_) ? ei[EE_ + e] : (e - EE_);
    atomicAdd(&g_cnt[dst], 1);
}
__global__ void scan_kernel() {
    __shared__ int sh[1024];
    int tid = threadIdx.x;
    int carry = 0;
    for (int base = 0; base < NN_; base += 1024) {
        int v = (base + tid < NN_) ? g_cnt[base + tid] : 0;
        sh[tid] = v;
        __syncthreads();
        for (int d = 1; d < 1024; d <<= 1) {
            int t = (tid >= d) ? sh[tid - d] : 0;
            __syncthreads();
            sh[tid] += t;
            __syncthreads();
        }
        if (base + tid < NN_) g_off[base + tid] = carry + sh[tid] - v;
        int tot = sh[1023];
        __syncthreads();
        carry += tot;
    }
    if (tid == 0) g_off[NN_] = carry;
}
__global__ void scatter_kernel(const int* __restrict__ ei) {
    int e = blockIdx.x * blockDim.x + threadIdx.x;
    if (e >= ETOT) return;
    int src, dst;
    if (e < EE_) { src = ei[e]; dst = ei[EE_ + e]; }
    else         { src = e - EE_; dst = e - EE_; }
    int pos = g_off[dst] + atomicAdd(&g_wpos[dst], 1);
    g_srcs[pos] = src;
}

// ---------------- unified bf16-split HMMA GEMM ------------------------------
// C[M, Ncols] = A[M,256] @ B[Ncols,256]^T, A/B given as bf16 hi+lo (3 segments).
// CTA = 128x128 tile, 8 warps (2x4), warp 64x32. K chunks of 64, double-buffered
// cp.async, swizzled smem, ldmatrix.x4 fragments.
// mode 0: store fp32. mode 1: sigmoid. mode 2: sigmoid + symmetric mirror
// (only tiles with bx >= by do work; result mirrored across the diagonal).

#define GBUF 32768   // bytes per (A+B) buffer: 2 x 128 rows x 128B

__global__ __launch_bounds__(256) void hmma_tt(
    const __nv_bfloat16* __restrict__ Ah, const __nv_bfloat16* __restrict__ Al,
    const __nv_bfloat16* __restrict__ Bh, const __nv_bfloat16* __restrict__ Bl,
    float* __restrict__ C, int M, int Ncols, size_t ldc, int mode)
{
    if (mode == 2 && blockIdx.x < blockIdx.y) return;

    extern __shared__ char dyn_smem[];
    uint32_t smem_base = smem_u32(dyn_smem);

    int tid = threadIdx.x;
    int wid = tid >> 5, lane = tid & 31;
    int wm = wid >> 2, wn = wid & 3;
    int g = lane >> 2, t = lane & 3;
    int m0 = blockIdx.y * 128, n0 = blockIdx.x * 128;

    const __nv_bfloat16* segA[3] = { Ah, Ah, Al };
    const __nv_bfloat16* segB[3] = { Bh, Bl, Bh };

    float acc[4][4][4];
#pragma unroll
    for (int i = 0; i < 4; i++)
#pragma unroll
        for (int j = 0; j < 4; j++)
#pragma unroll
            for (int k = 0; k < 4; k++) acc[i][j][k] = 0.f;

    auto issue_chunk = [&](int c, int buf) {
        int seg = c >> 2, k0 = (c & 3) * 64;
        const __nv_bfloat16* As = segA[seg];
        const __nv_bfloat16* Bs = segB[seg];
        uint32_t sa = smem_base + buf * GBUF;
        uint32_t sb = sa + 16384;
#pragma unroll
        for (int i = 0; i < 4; i++) {
            int idx = tid + i * 256;
            int r = idx >> 3, s16 = idx & 7;
            uint32_t off = (uint32_t)(r * 128 + ((s16 ^ (r & 7)) << 4));
            int gm = m0 + r;
            bool va = gm < M;
            cp16(sa + off, As + ((size_t)(va ? gm : 0) * F_ + k0 + s16 * 8), va);
            int gn = n0 + r;
            bool vb = gn < Ncols;
            cp16(sb + off, Bs + ((size_t)(vb ? gn : 0) * F_ + k0 + s16 * 8), vb);
        }
        cp_commit();
    };

    issue_chunk(0, 0);

    int lr = lane & 15;
    for (int c = 0; c < 12; c++) {
        cp_wait0();
        __syncthreads();
        if (c < 11) issue_chunk(c + 1, (c + 1) & 1);

        uint32_t sa = smem_base + (c & 1) * GBUF;
        uint32_t sb = sa + 16384;
#pragma unroll
        for (int ks = 0; ks < 4; ks++) {
            int lseg = 2 * ks + (lane >> 4);
            uint32_t af[4][4];
#pragma unroll
            for (int mt = 0; mt < 4; mt++) {
                int row = wm * 64 + mt * 16 + lr;
                uint32_t addr = sa + row * 128 + ((uint32_t)(lseg ^ (row & 7)) << 4);
                ldsm4(af[mt][0], af[mt][1], af[mt][2], af[mt][3], addr);
            }
            uint32_t bq[2][4];
#pragma unroll
            for (int hb = 0; hb < 2; hb++) {
                int row = wn * 32 + hb * 16 + lr;
                uint32_t addr = sb + row * 128 + ((uint32_t)(lseg ^ (row & 7)) << 4);
                ldsm4(bq[hb][0], bq[hb][1], bq[hb][2], bq[hb][3], addr);
            }
#pragma unroll
            for (int mt = 0; mt < 4; mt++)
#pragma unroll
                for (int nt = 0; nt < 4; nt++)
                    mma16816(acc[mt][nt],
                             af[mt][0], af[mt][1], af[mt][2], af[mt][3],
                             bq[nt >> 1][nt & 1], bq[nt >> 1][(nt & 1) + 2]);
        }
    }

    bool mirror = (mode == 2) && (blockIdx.x != blockIdx.y);

    // epilogue
#pragma unroll
    for (int mt = 0; mt < 4; mt++) {
        int gm = m0 + wm * 64 + mt * 16 + g;
#pragma unroll
        for (int nt = 0; nt < 4; nt++) {
            int gn = n0 + wn * 32 + nt * 8 + 2 * t;
            if (gn >= Ncols) continue;
            float* p0 = C + (size_t)gm * ldc + gn;
            if (mode == 0) {
                if (gm < M) {
                    float2 v = make_float2(acc[mt][nt][0], acc[mt][nt][1]);
                    *reinterpret_cast<float2*>(p0) = v;
                }
                if (gm + 8 < M) {
                    float2 v = make_float2(acc[mt][nt][2], acc[mt][nt][3]);
                    *reinterpret_cast<float2*>(p0 + 8 * ldc) = v;
                }
            } else {
                float s0 = 1.f / (1.f + __expf(-acc[mt][nt][0]));
                float s1 = 1.f / (1.f + __expf(-acc[mt][nt][1]));
                float s2 = 1.f / (1.f + __expf(-acc[mt][nt][2]));
                float s3 = 1.f / (1.f + __expf(-acc[mt][nt][3]));
                if (gm < M)
                    *reinterpret_cast<float2*>(p0) = make_float2(s0, s1);
                if (gm + 8 < M)
                    *reinterpret_cast<float2*>(p0 + 8 * ldc) = make_float2(s2, s3);
                if (mirror) {
                    // gn, gn+1 < Ncols (gn even, Ncols even)
                    float* q0 = C + (size_t)gn * ldc;
                    float* q1 = C + (size_t)(gn + 1) * ldc;
                    if (gm < M)     { q0[gm] = s0;     q1[gm] = s1; }
                    if (gm + 8 < M) { q0[gm + 8] = s2; q1[gm + 8] = s3; }
                }
            }
        }
    }
}

// ---------------- W transpose + hi/lo split ---------------------------------
__global__ void wt_split(const float* __restrict__ W) {
    __shared__ float tbuf[32][33];
    int bx = blockIdx.x, by = blockIdx.y;
    int x = threadIdx.x, y = threadIdx.y;
    for (int i = y; i < 32; i += 8)
        tbuf[i][x] = W[(size_t)(by * 32 + i) * HF_ + bx * 32 + x];
    __syncthreads();
    for (int i = y; i < 32; i += 8) {
        float v = tbuf[x][i];
        __nv_bfloat16 h = __float2bfloat16(v);
        size_t o = (size_t)(bx * 32 + i) * F_ + by * 32 + x;
        g_wth[o] = h;
        g_wtl[o] = __float2bfloat16(v - __bfloat162float(h));
    }
}

// ---------------- x -> bf16 hi/lo -------------------------------------------
__global__ void split_x(const float* __restrict__ x) {
    int i = blockIdx.x * blockDim.x + threadIdx.x;
    if (i >= NN_ * F_) return;
    float v = x[i];
    __nv_bfloat16 h = __float2bfloat16(v);
    g_bfh[i] = h;
    g_bfl[i] = __float2bfloat16(v - __bfloat162float(h));
}

// ---------------- attention logits ------------------------------------------
__global__ void attn_kernel(const float* __restrict__ a_src,
                            const float* __restrict__ a_dst)
{
    int n = blockIdx.x;
    int w = threadIdx.x / 32;
    int lane = threadIdx.x % 32;
    const float* hp = &g_h[(size_t)n * HF_ + w * F_];
    float ss = 0.f, sd = 0.f;
#pragma unroll
    for (int f = lane; f < F_; f += 32) {
        float hv = hp[f];
        ss += hv * a_src[w * F_ + f];
        sd += hv * a_dst[w * F_ + f];
    }
#pragma unroll
    for (int o = 16; o; o >>= 1) {
        ss += __shfl_down_sync(0xffffffffu, ss, o);
        sd += __shfl_down_sync(0xffffffffu, sd, o);
    }
    if (lane == 0) {
        g_als[n * H_ + w] = ss;
        g_ald[n * H_ + w] = sd;
    }
}

// ---------------- per-dst softmax + aggregation (+ bf16 split out) ----------
__device__ __forceinline__ float leaky(float x) {
    return x > 0.f ? x : LEAKY * x;
}

__global__ __launch_bounds__(256) void aggregate(
    const float* __restrict__ bias, float* __restrict__ xout, int mode)
{
    __shared__ float red[256];
    __shared__ float sm[H_], ssum[H_];
    __shared__ float alpha_sh[CH][H_];
    __shared__ int   src_sh[CH];

    int n = blockIdx.x, tid = threadIdx.x;
    int beg = g_off[n];
    int deg = g_off[n + 1] - beg;

    float ald[H_];
#pragma unroll
    for (int h = 0; h < H_; h++) ald[h] = g_ald[n * H_ + h];

    float mloc[H_];
#pragma unroll
    for (int h = 0; h < H_; h++) mloc[h] = -1e30f;
#pragma unroll 4
    for (int i = tid; i < deg; i += 256) {
        int s = g_srcs[beg + i];
#pragma unroll
        for (int h = 0; h < H_; h++) {
            float e = leaky(g_als[s * H_ + h] + ald[h]);
            mloc[h] = fmaxf(mloc[h], e);
        }
    }
#pragma unroll
    for (int h = 0; h < H_; h++) {
        red[tid] = mloc[h];
        __syncthreads();
        for (int o = 128; o; o >>= 1) {
            if (tid < o) red[tid] = fmaxf(red[tid], red[tid + o]);
            __syncthreads();
        }
        if (tid == 0) sm[h] = red[0];
        __syncthreads();
    }

    float sloc[H_] = {0.f, 0.f, 0.f, 0.f};
#pragma unroll 4
    for (int i = tid; i < deg; i += 256) {
        int s = g_srcs[beg + i];
#pragma unroll
        for (int h = 0; h < H_; h++) {
            float e = leaky(g_als[s * H_ + h] + ald[h]);
            sloc[h] += expf(e - sm[h]);
        }
    }
#pragma unroll
    for (int h = 0; h < H_; h++) {
        red[tid] = sloc[h];
        __syncthreads();
        for (int o = 128; o; o >>= 1) {
            if (tid < o) red[tid] += red[tid + o];
            __syncthreads();
        }
        if (tid == 0) ssum[h] = red[0];
        __syncthreads();
    }

    float acc[H_] = {0.f, 0.f, 0.f, 0.f};
    for (int base = 0; base < deg; base += CH) {
        int c = min(CH, deg - base);
        __syncthreads();
        for (int i = tid; i < c; i += 256) {
            int s = g_srcs[beg + base + i];
            src_sh[i] = s;
#pragma unroll
            for (int h = 0; h < H_; h++) {
                float e = leaky(g_als[s * H_ + h] + ald[h]);
                alpha_sh[i][h] = expf(e - sm[h]) / (ssum[h] + 1e-16f);
            }
        }
        __syncthreads();
        int j = 0;
        for (; j + 2 <= c; j += 2) {
            int s0 = src_sh[j], s1 = src_sh[j + 1];
            const float* hp0 = &g_h[(size_t)s0 * HF_ + tid];
            const float* hp1 = &g_h[(size_t)s1 * HF_ + tid];
            float b00 = hp0[0 * F_], b01 = hp0[1 * F_], b02 = hp0[2 * F_], b03 = hp0[3 * F_];
            float b10 = hp1[0 * F_], b11 = hp1[1 * F_], b12 = hp1[2 * F_], b13 = hp1[3 * F_];
            float a00 = alpha_sh[j][0], a01 = alpha_sh[j][1];
            float a02 = alpha_sh[j][2], a03 = alpha_sh[j][3];
            float a10 = alpha_sh[j + 1][0], a11 = alpha_sh[j + 1][1];
            float a12 = alpha_sh[j + 1][2], a13 = alpha_sh[j + 1][3];
            acc[0] += a00 * b00 + a10 * b10;
            acc[1] += a01 * b01 + a11 * b11;
            acc[2] += a02 * b02 + a12 * b12;
            acc[3] += a03 * b03 + a13 * b13;
        }
        if (j < c) {
            int s0 = src_sh[j];
            const float* hp0 = &g_h[(size_t)s0 * HF_ + tid];
            acc[0] += alpha_sh[j][0] * hp0[0 * F_];
            acc[1] += alpha_sh[j][1] * hp0[1 * F_];
            acc[2] += alpha_sh[j][2] * hp0[2 * F_];
            acc[3] += alpha_sh[j][3] * hp0[3 * F_];
        }
    }

    float v = (acc[0] + acc[1] + acc[2] + acc[3]) * 0.25f + bias[tid];
    v = mode ? tanhf(v) : fmaxf(v, 0.f);
    size_t o = (size_t)n * F_ + tid;
    xout[o] = v;
    __nv_bfloat16 hh = __float2bfloat16(v);
    g_bfh[o] = hh;
    g_bfl[o] = __float2bfloat16(v - __bfloat162float(hh));
}

// ---------------- driver ----------------------------------------------------
extern "C" void kernel_launch(void* const* d_in, const int* in_sizes, int n_in,
                              void* d_out, int out_size)
{
    const float* x  = (const float*)d_in[0];
    const int*   ei = (const int*)d_in[1];
    const float* W[4];  const float* as_[4]; const float* ad_[4]; const float* b_[4];
    for (int l = 0; l < 4; l++) {
        W[l]   = (const float*)d_in[2 + 4 * l];
        as_[l] = (const float*)d_in[3 + 4 * l];
        ad_[l] = (const float*)d_in[4 + 4 * l];
        b_[l]  = (const float*)d_in[5 + 4 * l];
    }
    float* out = (float*)d_out;

    float *p_h, *p_act0, *p_z;
    __nv_bfloat16 *p_bfh, *p_bfl, *p_wth, *p_wtl;
    cudaGetSymbolAddress((void**)&p_h,    g_h);
    cudaGetSymbolAddress((void**)&p_act0, g_act0);
    cudaGetSymbolAddress((void**)&p_z,    g_zbuf);
    cudaGetSymbolAddress((void**)&p_bfh,  g_bfh);
    cudaGetSymbolAddress((void**)&p_bfl,  g_bfl);
    cudaGetSymbolAddress((void**)&p_wth,  g_wth);
    cudaGetSymbolAddress((void**)&p_wtl,  g_wtl);

    const size_t ADJ = (size_t)NN_ * NN_;
    bool z_in_out = ((size_t)out_size >= ADJ + (size_t)NN_ * F_);
    float* zptr = z_in_out ? (out + ADJ) : p_z;

    static bool smem_attr = false;
    if (!smem_attr) {
        cudaFuncSetAttribute(hmma_tt, cudaFuncAttributeMaxDynamicSharedMemorySize,
                             2 * GBUF);
        smem_attr = true;
    }

    // ---- CSR build ----
    zero_int2<<<(NN_ + 255) / 256, 256>>>();
    count_kernel<<<(ETOT + 255) / 256, 256>>>(ei);
    scan_kernel<<<1, 1024>>>();
    scatter_kernel<<<(ETOT + 255) / 256, 256>>>(ei);

    // ---- 4 GAT layers ----
    split_x<<<(NN_ * F_ + 255) / 256, 256>>>(x);
    dim3 lgrid(HF_ / 128, (NN_ + 127) / 128);
    for (int l = 0; l < 4; l++) {
        wt_split<<<dim3(32, 8), dim3(32, 8)>>>(W[l]);
        hmma_tt<<<lgrid, 256, 2 * GBUF>>>(p_bfh, p_bfl, p_wth, p_wtl,
                                          p_h, NN_, HF_, HF_, 0);
        attn_kernel<<<NN_, H_ * 32>>>(as_[l], ad_[l]);
        aggregate<<<NN_, 256>>>(b_[l], (l == 3) ? zptr : p_act0, (l == 3) ? 1 : 0);
    }

    // ---- adj_recon = sigmoid(z @ z^T), symmetric: upper tiles + mirror ----
    dim3 fgrid((NN_ + 127) / 128, (NN_ + 127) / 128);
    hmma_tt<<<fgrid, 256, 2 * GBUF>>>(p_bfh, p_bfl, p_bfh, p_bfl,
                                      out, NN_, NN_, NN_, 2);
}

// round 6
// speedup vs baseline: 3.2807x; 1.1668x over previous
#include <cuda_runtime.h>
#include <cuda_bf16.h>
#include <math.h>
#include <stdint.h>

#define NN_   10000
#define EE_   320000
#define ETOT  (EE_ + NN_)
#define H_    4
#define F_    256
#define HF_   1024
#define LEAKY 0.2f
#define CH    128

// ---------------- scratch (device globals) ----------------------------------
__device__ float g_h[(size_t)NN_ * HF_];
__device__ float g_als[NN_ * H_];
__device__ float g_ald[NN_ * H_];
__device__ float g_act0[(size_t)NN_ * F_];
__device__ float g_zbuf[(size_t)NN_ * F_];
__device__ int   g_cnt[NN_];
__device__ int   g_off[NN_ + 1];
__device__ int   g_wpos[NN_];
__device__ int   g_srcs[ETOT];
__device__ __align__(16) __nv_bfloat16 g_bfh[(size_t)NN_ * F_];
__device__ __align__(16) __nv_bfloat16 g_bfl[(size_t)NN_ * F_];
__device__ __align__(16) __nv_bfloat16 g_wth[(size_t)HF_ * F_];
__device__ __align__(16) __nv_bfloat16 g_wtl[(size_t)HF_ * F_];

// ---------------- small PTX helpers -----------------------------------------
__device__ __forceinline__ uint32_t smem_u32(const void* p) {
    uint32_t a;
    asm("{ .reg .u64 t; cvta.to.shared.u64 t, %1; cvt.u32.u64 %0, t; }" : "=r"(a) : "l"(p));
    return a;
}
__device__ __forceinline__ void cp16(uint32_t dst, const void* src, bool valid) {
    int sz = valid ? 16 : 0;
    asm volatile("cp.async.cg.shared.global [%0], [%1], 16, %2;"
                 :: "r"(dst), "l"(src), "r"(sz) : "memory");
}
__device__ __forceinline__ void cp_commit() {
    asm volatile("cp.async.commit_group;" ::: "memory");
}
__device__ __forceinline__ void cp_wait0() {
    asm volatile("cp.async.wait_group 0;" ::: "memory");
}
__device__ __forceinline__ void ldsm4(uint32_t& r0, uint32_t& r1, uint32_t& r2,
                                      uint32_t& r3, uint32_t a) {
    asm volatile("ldmatrix.sync.aligned.m8n8.x4.shared.b16 {%0,%1,%2,%3}, [%4];"
                 : "=r"(r0), "=r"(r1), "=r"(r2), "=r"(r3) : "r"(a));
}
__device__ __forceinline__ void mma16816(float c[4], uint32_t a0, uint32_t a1,
                                         uint32_t a2, uint32_t a3,
                                         uint32_t b0, uint32_t b1) {
    asm volatile(
        "mma.sync.aligned.m16n8k16.row.col.f32.bf16.bf16.f32 "
        "{%0,%1,%2,%3}, {%4,%5,%6,%7}, {%8,%9}, {%0,%1,%2,%3};"
        : "+f"(c[0]), "+f"(c[1]), "+f"(c[2]), "+f"(c[3])
        : "r"(a0), "r"(a1), "r"(a2), "r"(a3), "r"(b0), "r"(b1));
}

// ---------------- CSR build -------------------------------------------------
__global__ void zero_int2() {
    int i = blockIdx.x * blockDim.x + threadIdx.x;
    if (i < NN_) { g_cnt[i] = 0; g_wpos[i] = 0; }
}
__global__ void count_kernel(const int* __restrict__ ei) {
    int e = blockIdx.x * blockDim.x + threadIdx.x;
    if (e >= ETOT) return;
    int dst = (e < EE_) ? ei[EE_ + e] : (e - EE_);
    atomicAdd(&g_cnt[dst], 1);
}
__global__ void scan_kernel() {
    __shared__ int sh[1024];
    int tid = threadIdx.x;
    int carry = 0;
    for (int base = 0; base < NN_; base += 1024) {
        int v = (base + tid < NN_) ? g_cnt[base + tid] : 0;
        sh[tid] = v;
        __syncthreads();
        for (int d = 1; d < 1024; d <<= 1) {
            int t = (tid >= d) ? sh[tid - d] : 0;
            __syncthreads();
            sh[tid] += t;
            __syncthreads();
        }
        if (base + tid < NN_) g_off[base + tid] = carry + sh[tid] - v;
        int tot = sh[1023];
        __syncthreads();
        carry += tot;
    }
    if (tid == 0) g_off[NN_] = carry;
}
__global__ void scatter_kernel(const int* __restrict__ ei) {
    int e = blockIdx.x * blockDim.x + threadIdx.x;
    if (e >= ETOT) return;
    int src, dst;
    if (e < EE_) { src = ei[e]; dst = ei[EE_ + e]; }
    else         { src = e - EE_; dst = e - EE_; }
    int pos = g_off[dst] + atomicAdd(&g_wpos[dst], 1);
    g_srcs[pos] = src;
}

// ---------------- unified bf16-split HMMA GEMM ------------------------------
#define GBUF 32768

__global__ __launch_bounds__(256) void hmma_tt(
    const __nv_bfloat16* __restrict__ Ah, const __nv_bfloat16* __restrict__ Al,
    const __nv_bfloat16* __restrict__ Bh, const __nv_bfloat16* __restrict__ Bl,
    float* __restrict__ C, int M, int Ncols, size_t ldc, int mode)
{
    if (mode == 2 && blockIdx.x < blockIdx.y) return;

    extern __shared__ char dyn_smem[];
    uint32_t smem_base = smem_u32(dyn_smem);

    int tid = threadIdx.x;
    int wid = tid >> 5, lane = tid & 31;
    int wm = wid >> 2, wn = wid & 3;
    int g = lane >> 2, t = lane & 3;
    int m0 = blockIdx.y * 128, n0 = blockIdx.x * 128;

    const __nv_bfloat16* segA[3] = { Ah, Ah, Al };
    const __nv_bfloat16* segB[3] = { Bh, Bl, Bh };

    float acc[4][4][4];
#pragma unroll
    for (int i = 0; i < 4; i++)
#pragma unroll
        for (int j = 0; j < 4; j++)
#pragma unroll
            for (int k = 0; k < 4; k++) acc[i][j][k] = 0.f;

    auto issue_chunk = [&](int c, int buf) {
        int seg = c >> 2, k0 = (c & 3) * 64;
        const __nv_bfloat16* As = segA[seg];
        const __nv_bfloat16* Bs = segB[seg];
        uint32_t sa = smem_base + buf * GBUF;
        uint32_t sb = sa + 16384;
#pragma unroll
        for (int i = 0; i < 4; i++) {
            int idx = tid + i * 256;
            int r = idx >> 3, s16 = idx & 7;
            uint32_t off = (uint32_t)(r * 128 + ((s16 ^ (r & 7)) << 4));
            int gm = m0 + r;
            bool va = gm < M;
            cp16(sa + off, As + ((size_t)(va ? gm : 0) * F_ + k0 + s16 * 8), va);
            int gn = n0 + r;
            bool vb = gn < Ncols;
            cp16(sb + off, Bs + ((size_t)(vb ? gn : 0) * F_ + k0 + s16 * 8), vb);
        }
        cp_commit();
    };

    issue_chunk(0, 0);

    int lr = lane & 15;
    for (int c = 0; c < 12; c++) {
        cp_wait0();
        __syncthreads();
        if (c < 11) issue_chunk(c + 1, (c + 1) & 1);

        uint32_t sa = smem_base + (c & 1) * GBUF;
        uint32_t sb = sa + 16384;
#pragma unroll
        for (int ks = 0; ks < 4; ks++) {
            int lseg = 2 * ks + (lane >> 4);
            uint32_t af[4][4];
#pragma unroll
            for (int mt = 0; mt < 4; mt++) {
                int row = wm * 64 + mt * 16 + lr;
                uint32_t addr = sa + row * 128 + ((uint32_t)(lseg ^ (row & 7)) << 4);
                ldsm4(af[mt][0], af[mt][1], af[mt][2], af[mt][3], addr);
            }
            uint32_t bq[2][4];
#pragma unroll
            for (int hb = 0; hb < 2; hb++) {
                int row = wn * 32 + hb * 16 + lr;
                uint32_t addr = sb + row * 128 + ((uint32_t)(lseg ^ (row & 7)) << 4);
                ldsm4(bq[hb][0], bq[hb][1], bq[hb][2], bq[hb][3], addr);
            }
#pragma unroll
            for (int mt = 0; mt < 4; mt++)
#pragma unroll
                for (int nt = 0; nt < 4; nt++)
                    mma16816(acc[mt][nt],
                             af[mt][0], af[mt][1], af[mt][2], af[mt][3],
                             bq[nt >> 1][nt & 1], bq[nt >> 1][(nt & 1) + 2]);
        }
    }

    bool mirror = (mode == 2) && (blockIdx.x != blockIdx.y);

#pragma unroll
    for (int mt = 0; mt < 4; mt++) {
        int gm = m0 + wm * 64 + mt * 16 + g;
#pragma unroll
        for (int nt = 0; nt < 4; nt++) {
            int gn = n0 + wn * 32 + nt * 8 + 2 * t;
            if (gn >= Ncols) continue;
            float* p0 = C + (size_t)gm * ldc + gn;
            if (mode == 0) {
                if (gm < M)
                    *reinterpret_cast<float2*>(p0) =
                        make_float2(acc[mt][nt][0], acc[mt][nt][1]);
                if (gm + 8 < M)
                    *reinterpret_cast<float2*>(p0 + 8 * ldc) =
                        make_float2(acc[mt][nt][2], acc[mt][nt][3]);
            } else {
                float s0 = 1.f / (1.f + __expf(-acc[mt][nt][0]));
                float s1 = 1.f / (1.f + __expf(-acc[mt][nt][1]));
                float s2 = 1.f / (1.f + __expf(-acc[mt][nt][2]));
                float s3 = 1.f / (1.f + __expf(-acc[mt][nt][3]));
                if (gm < M)
                    *reinterpret_cast<float2*>(p0) = make_float2(s0, s1);
                if (gm + 8 < M)
                    *reinterpret_cast<float2*>(p0 + 8 * ldc) = make_float2(s2, s3);
                if (mirror) {
                    float* q0 = C + (size_t)gn * ldc;
                    float* q1 = C + (size_t)(gn + 1) * ldc;
                    if (gm < M)     { q0[gm] = s0;     q1[gm] = s1; }
                    if (gm + 8 < M) { q0[gm + 8] = s2; q1[gm + 8] = s3; }
                }
            }
        }
    }
}

// ---------------- W transpose + hi/lo split ---------------------------------
__global__ void wt_split(const float* __restrict__ W) {
    __shared__ float tbuf[32][33];
    int bx = blockIdx.x, by = blockIdx.y;
    int x = threadIdx.x, y = threadIdx.y;
    for (int i = y; i < 32; i += 8)
        tbuf[i][x] = W[(size_t)(by * 32 + i) * HF_ + bx * 32 + x];
    __syncthreads();
    for (int i = y; i < 32; i += 8) {
        float v = tbuf[x][i];
        __nv_bfloat16 h = __float2bfloat16(v);
        size_t o = (size_t)(bx * 32 + i) * F_ + by * 32 + x;
        g_wth[o] = h;
        g_wtl[o] = __float2bfloat16(v - __bfloat162float(h));
    }
}

// ---------------- x -> bf16 hi/lo -------------------------------------------
__global__ void split_x(const float* __restrict__ x) {
    int i = blockIdx.x * blockDim.x + threadIdx.x;
    if (i >= NN_ * F_) return;
    float v = x[i];
    __nv_bfloat16 h = __float2bfloat16(v);
    g_bfh[i] = h;
    g_bfl[i] = __float2bfloat16(v - __bfloat162float(h));
}

// ---------------- attention logits (float4, 4 warps = 4 heads) -------------
__global__ __launch_bounds__(128) void attn_kernel(
    const float* __restrict__ a_src, const float* __restrict__ a_dst)
{
    int n = blockIdx.x;
    int w = threadIdx.x >> 5;
    int lane = threadIdx.x & 31;
    const float4* hp  = reinterpret_cast<const float4*>(&g_h[(size_t)n * HF_ + w * F_]);
    const float4* as4 = reinterpret_cast<const float4*>(a_src + w * F_);
    const float4* ad4 = reinterpret_cast<const float4*>(a_dst + w * F_);
    float ss = 0.f, sd = 0.f;
#pragma unroll
    for (int f = lane; f < 64; f += 32) {
        float4 h4 = hp[f], a4 = as4[f], d4 = ad4[f];
        ss += h4.x * a4.x + h4.y * a4.y + h4.z * a4.z + h4.w * a4.w;
        sd += h4.x * d4.x + h4.y * d4.y + h4.z * d4.z + h4.w * d4.w;
    }
#pragma unroll
    for (int o = 16; o; o >>= 1) {
        ss += __shfl_down_sync(0xffffffffu, ss, o);
        sd += __shfl_down_sync(0xffffffffu, sd, o);
    }
    if (lane == 0) {
        g_als[n * H_ + w] = ss;
        g_ald[n * H_ + w] = sd;
    }
}

// ---------------- per-dst online softmax + aggregation ----------------------
__device__ __forceinline__ float leaky(float x) {
    return x > 0.f ? x : LEAKY * x;
}

__global__ __launch_bounds__(256) void aggregate(
    const float* __restrict__ bias, float* __restrict__ xout, int mode)
{
    __shared__ float swm[8][H_], sws[8][H_];
    __shared__ float s_m[H_], s_inv[H_];
    __shared__ float alpha_sh[CH][H_];
    __shared__ int   src_sh[CH];

    int n = blockIdx.x, tid = threadIdx.x;
    int wid = tid >> 5, lane = tid & 31;
    int beg = g_off[n];
    int deg = g_off[n + 1] - beg;

    float ald[H_];
#pragma unroll
    for (int h = 0; h < H_; h++) ald[h] = g_ald[n * H_ + h];

    // single-scan online softmax (m, s) per head
    float m[H_], s[H_];
#pragma unroll
    for (int h = 0; h < H_; h++) { m[h] = -1e30f; s[h] = 0.f; }
    for (int i = tid; i < deg; i += 256) {
        int sc = g_srcs[beg + i];
#pragma unroll
        for (int h = 0; h < H_; h++) {
            float e = leaky(g_als[sc * H_ + h] + ald[h]);
            if (e > m[h]) { s[h] = s[h] * __expf(m[h] - e) + 1.f; m[h] = e; }
            else          s[h] += __expf(e - m[h]);
        }
    }
    // warp combine
#pragma unroll
    for (int o = 16; o; o >>= 1) {
#pragma unroll
        for (int h = 0; h < H_; h++) {
            float mo = __shfl_down_sync(0xffffffffu, m[h], o);
            float so = __shfl_down_sync(0xffffffffu, s[h], o);
            float mn = fmaxf(m[h], mo);
            s[h] = s[h] * __expf(m[h] - mn) + so * __expf(mo - mn);
            m[h] = mn;
        }
    }
    if (lane == 0)
#pragma unroll
        for (int h = 0; h < H_; h++) { swm[wid][h] = m[h]; sws[wid][h] = s[h]; }
    __syncthreads();
    if (tid < 32) {
        bool v = lane < 8;
#pragma unroll
        for (int h = 0; h < H_; h++) {
            m[h] = v ? swm[lane][h] : -1e30f;
            s[h] = v ? sws[lane][h] : 0.f;
        }
#pragma unroll
        for (int o = 4; o; o >>= 1) {
#pragma unroll
            for (int h = 0; h < H_; h++) {
                float mo = __shfl_down_sync(0xffffffffu, m[h], o);
                float so = __shfl_down_sync(0xffffffffu, s[h], o);
                float mn = fmaxf(m[h], mo);
                s[h] = s[h] * __expf(m[h] - mn) + so * __expf(mo - mn);
                m[h] = mn;
            }
        }
        if (lane == 0)
#pragma unroll
            for (int h = 0; h < H_; h++) {
                s_m[h]   = m[h];
                s_inv[h] = 1.f / (s[h] + 1e-16f);
            }
    }
    __syncthreads();

    float sm_r[H_], si_r[H_];
#pragma unroll
    for (int h = 0; h < H_; h++) { sm_r[h] = s_m[h]; si_r[h] = s_inv[h]; }

    // chunked alpha + weighted aggregation (thread tid = feature column)
    float acc[H_] = {0.f, 0.f, 0.f, 0.f};
    for (int base = 0; base < deg; base += CH) {
        int c = min(CH, deg - base);
        __syncthreads();
        for (int i = tid; i < c; i += 256) {
            int sc = g_srcs[beg + base + i];
            src_sh[i] = sc;
#pragma unroll
            for (int h = 0; h < H_; h++) {
                float e = leaky(g_als[sc * H_ + h] + ald[h]);
                alpha_sh[i][h] = __expf(e - sm_r[h]) * si_r[h];
            }
        }
        __syncthreads();
        int j = 0;
        for (; j + 4 <= c; j += 4) {
            int s0 = src_sh[j],     s1 = src_sh[j + 1];
            int s2 = src_sh[j + 2], s3 = src_sh[j + 3];
            const float* h0 = &g_h[(size_t)s0 * HF_ + tid];
            const float* h1 = &g_h[(size_t)s1 * HF_ + tid];
            const float* h2 = &g_h[(size_t)s2 * HF_ + tid];
            const float* h3 = &g_h[(size_t)s3 * HF_ + tid];
#pragma unroll
            for (int h = 0; h < H_; h++) {
                acc[h] += alpha_sh[j][h]     * h0[h * F_]
                        + alpha_sh[j + 1][h] * h1[h * F_]
                        + alpha_sh[j + 2][h] * h2[h * F_]
                        + alpha_sh[j + 3][h] * h3[h * F_];
            }
        }
        for (; j < c; j++) {
            int s0 = src_sh[j];
            const float* h0 = &g_h[(size_t)s0 * HF_ + tid];
#pragma unroll
            for (int h = 0; h < H_; h++)
                acc[h] += alpha_sh[j][h] * h0[h * F_];
        }
    }

    float v = (acc[0] + acc[1] + acc[2] + acc[3]) * 0.25f + bias[tid];
    v = mode ? tanhf(v) : fmaxf(v, 0.f);
    size_t o = (size_t)n * F_ + tid;
    xout[o] = v;
    __nv_bfloat16 hh = __float2bfloat16(v);
    g_bfh[o] = hh;
    g_bfl[o] = __float2bfloat16(v - __bfloat162float(hh));
}

// ---------------- driver ----------------------------------------------------
extern "C" void kernel_launch(void* const* d_in, const int* in_sizes, int n_in,
                              void* d_out, int out_size)
{
    const float* x  = (const float*)d_in[0];
    const int*   ei = (const int*)d_in[1];
    const float* W[4];  const float* as_[4]; const float* ad_[4]; const float* b_[4];
    for (int l = 0; l < 4; l++) {
        W[l]   = (const float*)d_in[2 + 4 * l];
        as_[l] = (const float*)d_in[3 + 4 * l];
        ad_[l] = (const float*)d_in[4 + 4 * l];
        b_[l]  = (const float*)d_in[5 + 4 * l];
    }
    float* out = (float*)d_out;

    float *p_h, *p_act0, *p_z;
    __nv_bfloat16 *p_bfh, *p_bfl, *p_wth, *p_wtl;
    cudaGetSymbolAddress((void**)&p_h,    g_h);
    cudaGetSymbolAddress((void**)&p_act0, g_act0);
    cudaGetSymbolAddress((void**)&p_z,    g_zbuf);
    cudaGetSymbolAddress((void**)&p_bfh,  g_bfh);
    cudaGetSymbolAddress((void**)&p_bfl,  g_bfl);
    cudaGetSymbolAddress((void**)&p_wth,  g_wth);
    cudaGetSymbolAddress((void**)&p_wtl,  g_wtl);

    const size_t ADJ = (size_t)NN_ * NN_;
    bool z_in_out = ((size_t)out_size >= ADJ + (size_t)NN_ * F_);
    float* zptr = z_in_out ? (out + ADJ) : p_z;

    static bool smem_attr = false;
    if (!smem_attr) {
        cudaFuncSetAttribute(hmma_tt, cudaFuncAttributeMaxDynamicSharedMemorySize,
                             2 * GBUF);
        smem_attr = true;
    }

    // ---- CSR build ----
    zero_int2<<<(NN_ + 255) / 256, 256>>>();
    count_kernel<<<(ETOT + 255) / 256, 256>>>(ei);
    scan_kernel<<<1, 1024>>>();
    scatter_kernel<<<(ETOT + 255) / 256, 256>>>(ei);

    // ---- 4 GAT layers ----
    split_x<<<(NN_ * F_ + 255) / 256, 256>>>(x);
    dim3 lgrid(HF_ / 128, (NN_ + 127) / 128);
    for (int l = 0; l < 4; l++) {
        wt_split<<<dim3(32, 8), dim3(32, 8)>>>(W[l]);
        hmma_tt<<<lgrid, 256, 2 * GBUF>>>(p_bfh, p_bfl, p_wth, p_wtl,
                                          p_h, NN_, HF_, HF_, 0);
        attn_kernel<<<NN_, 128>>>(as_[l], ad_[l]);
        aggregate<<<NN_, 256>>>(b_[l], (l == 3) ? zptr : p_act0, (l == 3) ? 1 : 0);
    }

    // ---- adj_recon = sigmoid(z @ z^T), symmetric upper + mirror ----
    dim3 fgrid((NN_ + 127) / 128, (NN_ + 127) / 128);
    hmma_tt<<<fgrid, 256, 2 * GBUF>>>(p_bfh, p_bfl, p_bfh, p_bfl,
                                      out, NN_, NN_, NN_, 2);
}

// round 7
// speedup vs baseline: 3.2999x; 1.0059x over previous
#include <cuda_runtime.h>
#include <cuda_bf16.h>
#include <math.h>
#include <stdint.h>

#define NN_   10000
#define EE_   320000
#define ETOT  (EE_ + NN_)
#define H_    4
#define F_    256
#define HF_   1024
#define LEAKY 0.2f
#define CH    128
#define NTILE 79                 // ceil(10000/128)
#define TRI   (NTILE * (NTILE + 1) / 2)

// ---------------- scratch (device globals) ----------------------------------
__device__ float g_h[(size_t)NN_ * HF_];
__device__ float g_als[NN_ * H_];
__device__ float g_ald[NN_ * H_];
__device__ float g_act0[(size_t)NN_ * F_];
__device__ float g_zbuf[(size_t)NN_ * F_];
__device__ int   g_cnt[NN_];
__device__ int   g_off[NN_ + 1];
__device__ int   g_wpos[NN_];
__device__ int   g_srcs[ETOT];
__device__ __align__(16) __nv_bfloat16 g_bfh[(size_t)NN_ * F_];
__device__ __align__(16) __nv_bfloat16 g_bfl[(size_t)NN_ * F_];
__device__ __align__(16) __nv_bfloat16 g_wth[(size_t)HF_ * F_];
__device__ __align__(16) __nv_bfloat16 g_wtl[(size_t)HF_ * F_];

// ---------------- small PTX helpers -----------------------------------------
__device__ __forceinline__ uint32_t smem_u32(const void* p) {
    uint32_t a;
    asm("{ .reg .u64 t; cvta.to.shared.u64 t, %1; cvt.u32.u64 %0, t; }" : "=r"(a) : "l"(p));
    return a;
}
__device__ __forceinline__ void cp16(uint32_t dst, const void* src, bool valid) {
    int sz = valid ? 16 : 0;
    asm volatile("cp.async.cg.shared.global [%0], [%1], 16, %2;"
                 :: "r"(dst), "l"(src), "r"(sz) : "memory");
}
__device__ __forceinline__ void cp_commit() {
    asm volatile("cp.async.commit_group;" ::: "memory");
}
__device__ __forceinline__ void cp_wait0() {
    asm volatile("cp.async.wait_group 0;" ::: "memory");
}
__device__ __forceinline__ void ldsm4(uint32_t& r0, uint32_t& r1, uint32_t& r2,
                                      uint32_t& r3, uint32_t a) {
    asm volatile("ldmatrix.sync.aligned.m8n8.x4.shared.b16 {%0,%1,%2,%3}, [%4];"
                 : "=r"(r0), "=r"(r1), "=r"(r2), "=r"(r3) : "r"(a));
}
__device__ __forceinline__ void mma16816(float c[4], uint32_t a0, uint32_t a1,
                                         uint32_t a2, uint32_t a3,
                                         uint32_t b0, uint32_t b1) {
    asm volatile(
        "mma.sync.aligned.m16n8k16.row.col.f32.bf16.bf16.f32 "
        "{%0,%1,%2,%3}, {%4,%5,%6,%7}, {%8,%9}, {%0,%1,%2,%3};"
        : "+f"(c[0]), "+f"(c[1]), "+f"(c[2]), "+f"(c[3])
        : "r"(a0), "r"(a1), "r"(a2), "r"(a3), "r"(b0), "r"(b1));
}

// ---------------- CSR build -------------------------------------------------
__global__ void zero_int2() {
    int i = blockIdx.x * blockDim.x + threadIdx.x;
    if (i < NN_) { g_cnt[i] = 0; g_wpos[i] = 0; }
}
__global__ void count_kernel(const int* __restrict__ ei) {
    int e = blockIdx.x * blockDim.x + threadIdx.x;
    if (e >= ETOT) return;
    int dst = (e < EE_) ? ei[EE_ + e] : (e - EE_);
    atomicAdd(&g_cnt[dst], 1);
}
__global__ void scan_kernel() {
    __shared__ int sh[1024];
    int tid = threadIdx.x;
    int carry = 0;
    for (int base = 0; base < NN_; base += 1024) {
        int v = (base + tid < NN_) ? g_cnt[base + tid] : 0;
        sh[tid] = v;
        __syncthreads();
        for (int d = 1; d < 1024; d <<= 1) {
            int t = (tid >= d) ? sh[tid - d] : 0;
            __syncthreads();
            sh[tid] += t;
            __syncthreads();
        }
        if (base + tid < NN_) g_off[base + tid] = carry + sh[tid] - v;
        int tot = sh[1023];
        __syncthreads();
        carry += tot;
    }
    if (tid == 0) g_off[NN_] = carry;
}
__global__ void scatter_kernel(const int* __restrict__ ei) {
    int e = blockIdx.x * blockDim.x + threadIdx.x;
    if (e >= ETOT) return;
    int src, dst;
    if (e < EE_) { src = ei[e]; dst = ei[EE_ + e]; }
    else         { src = e - EE_; dst = e - EE_; }
    int pos = g_off[dst] + atomicAdd(&g_wpos[dst], 1);
    g_srcs[pos] = src;
}

// ---------------- zero attention accumulators --------------------------------
__global__ void zero_attn() {
    int i = blockIdx.x * blockDim.x + threadIdx.x;
    if (i < NN_ * H_) { g_als[i] = 0.f; g_ald[i] = 0.f; }
}

// ---------------- unified bf16-split HMMA GEMM ------------------------------
// C[M, Ncols] = A[M,256] @ B[Ncols,256]^T, bf16 hi/lo split (3 segments).
// mode 0: store fp32 + fused attn-logit partial dots into g_als/g_ald.
// mode 2: sigmoid + symmetric mirror, 1D triangular grid.
#define GBUF 32768

__global__ __launch_bounds__(256) void hmma_tt(
    const __nv_bfloat16* __restrict__ Ah, const __nv_bfloat16* __restrict__ Al,
    const __nv_bfloat16* __restrict__ Bh, const __nv_bfloat16* __restrict__ Bl,
    const float* __restrict__ asrc, const float* __restrict__ adst,
    float* __restrict__ C, int M, int Ncols, size_t ldc, int mode)
{
    extern __shared__ char dyn_smem[];
    uint32_t smem_base = smem_u32(dyn_smem);

    int tid = threadIdx.x;
    int wid = tid >> 5, lane = tid & 31;
    int wm = wid >> 2, wn = wid & 3;
    int g = lane >> 2, t = lane & 3;

    int bx, by;
    if (mode == 2) {
        int j = blockIdx.x;
        bx = (int)((sqrtf(8.f * j + 1.f) - 1.f) * 0.5f);
        while ((bx + 1) * (bx + 2) / 2 <= j) bx++;
        while (bx * (bx + 1) / 2 > j) bx--;
        by = j - bx * (bx + 1) / 2;
    } else {
        bx = blockIdx.x; by = blockIdx.y;
    }
    int m0 = by * 128, n0 = bx * 128;

    const __nv_bfloat16* segA[3] = { Ah, Ah, Al };
    const __nv_bfloat16* segB[3] = { Bh, Bl, Bh };

    float acc[4][4][4];
#pragma unroll
    for (int i = 0; i < 4; i++)
#pragma unroll
        for (int j2 = 0; j2 < 4; j2++)
#pragma unroll
            for (int k = 0; k < 4; k++) acc[i][j2][k] = 0.f;

    auto issue_chunk = [&](int c, int buf) {
        int seg = c >> 2, k0 = (c & 3) * 64;
        const __nv_bfloat16* As = segA[seg];
        const __nv_bfloat16* Bs = segB[seg];
        uint32_t sa = smem_base + buf * GBUF;
        uint32_t sb = sa + 16384;
#pragma unroll
        for (int i = 0; i < 4; i++) {
            int idx = tid + i * 256;
            int r = idx >> 3, s16 = idx & 7;
            uint32_t off = (uint32_t)(r * 128 + ((s16 ^ (r & 7)) << 4));
            int gm = m0 + r;
            bool va = gm < M;
            cp16(sa + off, As + ((size_t)(va ? gm : 0) * F_ + k0 + s16 * 8), va);
            int gn = n0 + r;
            bool vb = gn < Ncols;
            cp16(sb + off, Bs + ((size_t)(vb ? gn : 0) * F_ + k0 + s16 * 8), vb);
        }
        cp_commit();
    };

    issue_chunk(0, 0);

    int lr = lane & 15;
    for (int c = 0; c < 12; c++) {
        cp_wait0();
        __syncthreads();
        if (c < 11) issue_chunk(c + 1, (c + 1) & 1);

        uint32_t sa = smem_base + (c & 1) * GBUF;
        uint32_t sb = sa + 16384;
#pragma unroll
        for (int ks = 0; ks < 4; ks++) {
            int lseg = 2 * ks + (lane >> 4);
            uint32_t af[4][4];
#pragma unroll
            for (int mt = 0; mt < 4; mt++) {
                int row = wm * 64 + mt * 16 + lr;
                uint32_t addr = sa + row * 128 + ((uint32_t)(lseg ^ (row & 7)) << 4);
                ldsm4(af[mt][0], af[mt][1], af[mt][2], af[mt][3], addr);
            }
            uint32_t bq[2][4];
#pragma unroll
            for (int hb = 0; hb < 2; hb++) {
                int row = wn * 32 + hb * 16 + lr;
                uint32_t addr = sb + row * 128 + ((uint32_t)(lseg ^ (row & 7)) << 4);
                ldsm4(bq[hb][0], bq[hb][1], bq[hb][2], bq[hb][3], addr);
            }
#pragma unroll
            for (int mt = 0; mt < 4; mt++)
#pragma unroll
                for (int nt = 0; nt < 4; nt++)
                    mma16816(acc[mt][nt],
                             af[mt][0], af[mt][1], af[mt][2], af[mt][3],
                             bq[nt >> 1][nt & 1], bq[nt >> 1][(nt & 1) + 2]);
        }
    }

    if (mode == 0) {
        // store h tile + fused attention-logit partial dot products
        int head = n0 >> 8;              // which of 4 heads this 128-col tile is in
        int base = n0 & 255;             // feature offset within the head
        float a0v[4], a1v[4], b0v[4], b1v[4];
#pragma unroll
        for (int nt = 0; nt < 4; nt++) {
            int f = head * 256 + base + wn * 32 + nt * 8 + 2 * t;
            a0v[nt] = asrc[f];  a1v[nt] = asrc[f + 1];
            b0v[nt] = adst[f];  b1v[nt] = adst[f + 1];
        }
#pragma unroll
        for (int mt = 0; mt < 4; mt++) {
            int gm = m0 + wm * 64 + mt * 16 + g;
            float s0 = 0.f, s1 = 0.f, d0 = 0.f, d1 = 0.f;
#pragma unroll
            for (int nt = 0; nt < 4; nt++) {
                int gn = n0 + wn * 32 + nt * 8 + 2 * t;
                float* p0 = C + (size_t)gm * ldc + gn;
                if (gm < M)
                    *reinterpret_cast<float2*>(p0) =
                        make_float2(acc[mt][nt][0], acc[mt][nt][1]);
                if (gm + 8 < M)
                    *reinterpret_cast<float2*>(p0 + 8 * ldc) =
                        make_float2(acc[mt][nt][2], acc[mt][nt][3]);
                s0 += acc[mt][nt][0] * a0v[nt] + acc[mt][nt][1] * a1v[nt];
                s1 += acc[mt][nt][2] * a0v[nt] + acc[mt][nt][3] * a1v[nt];
                d0 += acc[mt][nt][0] * b0v[nt] + acc[mt][nt][1] * b1v[nt];
                d1 += acc[mt][nt][2] * b0v[nt] + acc[mt][nt][3] * b1v[nt];
            }
#pragma unroll
            for (int o = 1; o <= 2; o <<= 1) {
                s0 += __shfl_xor_sync(0xffffffffu, s0, o);
                s1 += __shfl_xor_sync(0xffffffffu, s1, o);
                d0 += __shfl_xor_sync(0xffffffffu, d0, o);
                d1 += __shfl_xor_sync(0xffffffffu, d1, o);
            }
            if (t == 0) {
                if (gm < M) {
                    atomicAdd(&g_als[gm * H_ + head], s0);
                    atomicAdd(&g_ald[gm * H_ + head], d0);
                }
                if (gm + 8 < M) {
                    atomicAdd(&g_als[(gm + 8) * H_ + head], s1);
                    atomicAdd(&g_ald[(gm + 8) * H_ + head], d1);
                }
            }
        }
    } else {
        bool mirror = (bx != by);
#pragma unroll
        for (int mt = 0; mt < 4; mt++) {
            int gm = m0 + wm * 64 + mt * 16 + g;
#pragma unroll
            for (int nt = 0; nt < 4; nt++) {
                int gn = n0 + wn * 32 + nt * 8 + 2 * t;
                if (gn >= Ncols) continue;
                float* p0 = C + (size_t)gm * ldc + gn;
                float s0 = 1.f / (1.f + __expf(-acc[mt][nt][0]));
                float s1 = 1.f / (1.f + __expf(-acc[mt][nt][1]));
                float s2 = 1.f / (1.f + __expf(-acc[mt][nt][2]));
                float s3 = 1.f / (1.f + __expf(-acc[mt][nt][3]));
                if (gm < M)
                    *reinterpret_cast<float2*>(p0) = make_float2(s0, s1);
                if (gm + 8 < M)
                    *reinterpret_cast<float2*>(p0 + 8 * ldc) = make_float2(s2, s3);
                if (mirror) {
                    float* q0 = C + (size_t)gn * ldc;
                    float* q1 = C + (size_t)(gn + 1) * ldc;
                    if (gm < M)     { q0[gm] = s0;     q1[gm] = s1; }
                    if (gm + 8 < M) { q0[gm + 8] = s2; q1[gm + 8] = s3; }
                }
            }
        }
    }
}

// ---------------- W transpose + hi/lo split ---------------------------------
__global__ void wt_split(const float* __restrict__ W) {
    __shared__ float tbuf[32][33];
    int bx = blockIdx.x, by = blockIdx.y;
    int x = threadIdx.x, y = threadIdx.y;
    for (int i = y; i < 32; i += 8)
        tbuf[i][x] = W[(size_t)(by * 32 + i) * HF_ + bx * 32 + x];
    __syncthreads();
    for (int i = y; i < 32; i += 8) {
        float v = tbuf[x][i];
        __nv_bfloat16 h = __float2bfloat16(v);
        size_t o = (size_t)(bx * 32 + i) * F_ + by * 32 + x;
        g_wth[o] = h;
        g_wtl[o] = __float2bfloat16(v - __bfloat162float(h));
    }
}

// ---------------- x -> bf16 hi/lo -------------------------------------------
__global__ void split_x(const float* __restrict__ x) {
    int i = blockIdx.x * blockDim.x + threadIdx.x;
    if (i >= NN_ * F_) return;
    float v = x[i];
    __nv_bfloat16 h = __float2bfloat16(v);
    g_bfh[i] = h;
    g_bfl[i] = __float2bfloat16(v - __bfloat162float(h));
}

// ---------------- per-dst online softmax + aggregation ----------------------
__device__ __forceinline__ float leaky(float x) {
    return x > 0.f ? x : LEAKY * x;
}

__global__ __launch_bounds__(256) void aggregate(
    const float* __restrict__ bias, float* __restrict__ xout, int mode)
{
    __shared__ float swm[8][H_], sws[8][H_];
    __shared__ float s_m[H_], s_inv[H_];
    __shared__ float alpha_sh[CH][H_];
    __shared__ int   src_sh[CH];

    int n = blockIdx.x, tid = threadIdx.x;
    int wid = tid >> 5, lane = tid & 31;
    int beg = g_off[n];
    int deg = g_off[n + 1] - beg;

    float ald[H_];
#pragma unroll
    for (int h = 0; h < H_; h++) ald[h] = g_ald[n * H_ + h];

    float m[H_], s[H_];
#pragma unroll
    for (int h = 0; h < H_; h++) { m[h] = -1e30f; s[h] = 0.f; }
    for (int i = tid; i < deg; i += 256) {
        int sc = g_srcs[beg + i];
#pragma unroll
        for (int h = 0; h < H_; h++) {
            float e = leaky(g_als[sc * H_ + h] + ald[h]);
            if (e > m[h]) { s[h] = s[h] * __expf(m[h] - e) + 1.f; m[h] = e; }
            else          s[h] += __expf(e - m[h]);
        }
    }
#pragma unroll
    for (int o = 16; o; o >>= 1) {
#pragma unroll
        for (int h = 0; h < H_; h++) {
            float mo = __shfl_down_sync(0xffffffffu, m[h], o);
            float so = __shfl_down_sync(0xffffffffu, s[h], o);
            float mn = fmaxf(m[h], mo);
            s[h] = s[h] * __expf(m[h] - mn) + so * __expf(mo - mn);
            m[h] = mn;
        }
    }
    if (lane == 0)
#pragma unroll
        for (int h = 0; h < H_; h++) { swm[wid][h] = m[h]; sws[wid][h] = s[h]; }
    __syncthreads();
    if (tid < 32) {
        bool v = lane < 8;
#pragma unroll
        for (int h = 0; h < H_; h++) {
            m[h] = v ? swm[lane][h] : -1e30f;
            s[h] = v ? sws[lane][h] : 0.f;
        }
#pragma unroll
        for (int o = 4; o; o >>= 1) {
#pragma unroll
            for (int h = 0; h < H_; h++) {
                float mo = __shfl_down_sync(0xffffffffu, m[h], o);
                float so = __shfl_down_sync(0xffffffffu, s[h], o);
                float mn = fmaxf(m[h], mo);
                s[h] = s[h] * __expf(m[h] - mn) + so * __expf(mo - mn);
                m[h] = mn;
            }
        }
        if (lane == 0)
#pragma unroll
            for (int h = 0; h < H_; h++) {
                s_m[h]   = m[h];
                s_inv[h] = 1.f / (s[h] + 1e-16f);
            }
    }
    __syncthreads();

    float sm_r[H_], si_r[H_];
#pragma unroll
    for (int h = 0; h < H_; h++) { sm_r[h] = s_m[h]; si_r[h] = s_inv[h]; }

    float acc[H_] = {0.f, 0.f, 0.f, 0.f};
    for (int base = 0; base < deg; base += CH) {
        int c = min(CH, deg - base);
        __syncthreads();
        for (int i = tid; i < c; i += 256) {
            int sc = g_srcs[beg + base + i];
            src_sh[i] = sc;
#pragma unroll
            for (int h = 0; h < H_; h++) {
                float e = leaky(g_als[sc * H_ + h] + ald[h]);
                alpha_sh[i][h] = __expf(e - sm_r[h]) * si_r[h];
            }
        }
        __syncthreads();
        int j = 0;
        for (; j + 4 <= c; j += 4) {
            int s0 = src_sh[j],     s1 = src_sh[j + 1];
            int s2 = src_sh[j + 2], s3 = src_sh[j + 3];
            const float* h0 = &g_h[(size_t)s0 * HF_ + tid];
            const float* h1 = &g_h[(size_t)s1 * HF_ + tid];
            const float* h2 = &g_h[(size_t)s2 * HF_ + tid];
            const float* h3 = &g_h[(size_t)s3 * HF_ + tid];
#pragma unroll
            for (int h = 0; h < H_; h++) {
                acc[h] += alpha_sh[j][h]     * h0[h * F_]
                        + alpha_sh[j + 1][h] * h1[h * F_]
                        + alpha_sh[j + 2][h] * h2[h * F_]
                        + alpha_sh[j + 3][h] * h3[h * F_];
            }
        }
        for (; j < c; j++) {
            int s0 = src_sh[j];
            const float* h0 = &g_h[(size_t)s0 * HF_ + tid];
#pragma unroll
            for (int h = 0; h < H_; h++)
                acc[h] += alpha_sh[j][h] * h0[h * F_];
        }
    }

    float v = (acc[0] + acc[1] + acc[2] + acc[3]) * 0.25f + bias[tid];
    v = mode ? tanhf(v) : fmaxf(v, 0.f);
    size_t o = (size_t)n * F_ + tid;
    xout[o] = v;
    __nv_bfloat16 hh = __float2bfloat16(v);
    g_bfh[o] = hh;
    g_bfl[o] = __float2bfloat16(v - __bfloat162float(hh));
}

// ---------------- driver ----------------------------------------------------
extern "C" void kernel_launch(void* const* d_in, const int* in_sizes, int n_in,
                              void* d_out, int out_size)
{
    const float* x  = (const float*)d_in[0];
    const int*   ei = (const int*)d_in[1];
    const float* W[4];  const float* as_[4]; const float* ad_[4]; const float* b_[4];
    for (int l = 0; l < 4; l++) {
        W[l]   = (const float*)d_in[2 + 4 * l];
        as_[l] = (const float*)d_in[3 + 4 * l];
        ad_[l] = (const float*)d_in[4 + 4 * l];
        b_[l]  = (const float*)d_in[5 + 4 * l];
    }
    float* out = (float*)d_out;

    float *p_h, *p_act0, *p_z;
    __nv_bfloat16 *p_bfh, *p_bfl, *p_wth, *p_wtl;
    cudaGetSymbolAddress((void**)&p_h,    g_h);
    cudaGetSymbolAddress((void**)&p_act0, g_act0);
    cudaGetSymbolAddress((void**)&p_z,    g_zbuf);
    cudaGetSymbolAddress((void**)&p_bfh,  g_bfh);
    cudaGetSymbolAddress((void**)&p_bfl,  g_bfl);
    cudaGetSymbolAddress((void**)&p_wth,  g_wth);
    cudaGetSymbolAddress((void**)&p_wtl,  g_wtl);

    const size_t ADJ = (size_t)NN_ * NN_;
    bool z_in_out = ((size_t)out_size >= ADJ + (size_t)NN_ * F_);
    float* zptr = z_in_out ? (out + ADJ) : p_z;

    static bool smem_attr = false;
    if (!smem_attr) {
        cudaFuncSetAttribute(hmma_tt, cudaFuncAttributeMaxDynamicSharedMemorySize,
                             2 * GBUF);
        smem_attr = true;
    }

    dim3 lgrid(HF_ / 128, (NN_ + 127) / 128);

    // ---- layer 0 front (hmma_tt is 4th launch -> ncu target) ----
    split_x<<<(NN_ * F_ + 255) / 256, 256>>>(x);
    wt_split<<<dim3(32, 8), dim3(32, 8)>>>(W[0]);
    zero_attn<<<(NN_ * H_ + 255) / 256, 256>>>();
    hmma_tt<<<lgrid, 256, 2 * GBUF>>>(p_bfh, p_bfl, p_wth, p_wtl,
                                      as_[0], ad_[0], p_h, NN_, HF_, HF_, 0);

    // ---- CSR build (needed before first aggregate) ----
    zero_int2<<<(NN_ + 255) / 256, 256>>>();
    count_kernel<<<(ETOT + 255) / 256, 256>>>(ei);
    scan_kernel<<<1, 1024>>>();
    scatter_kernel<<<(ETOT + 255) / 256, 256>>>(ei);

    aggregate<<<NN_, 256>>>(b_[0], p_act0, 0);

    // ---- layers 1..3 ----
    for (int l = 1; l < 4; l++) {
        wt_split<<<dim3(32, 8), dim3(32, 8)>>>(W[l]);
        zero_attn<<<(NN_ * H_ + 255) / 256, 256>>>();
        hmma_tt<<<lgrid, 256, 2 * GBUF>>>(p_bfh, p_bfl, p_wth, p_wtl,
                                          as_[l], ad_[l], p_h, NN_, HF_, HF_, 0);
        aggregate<<<NN_, 256>>>(b_[l], (l == 3) ? zptr : p_act0, (l == 3) ? 1 : 0);
    }

    // ---- adj_recon = sigmoid(z @ z^T), triangular grid + mirror ----
    hmma_tt<<<TRI, 256, 2 * GBUF>>>(p_bfh, p_bfl, p_bfh, p_bfl,
                                    nullptr, nullptr, out, NN_, NN_, NN_, 2);
}

// round 8
// speedup vs baseline: 3.3129x; 1.0039x over previous
#include <cuda_runtime.h>
#include <cuda_bf16.h>
#include <math.h>
#include <stdint.h>

#define NN_   10000
#define EE_   320000
#define ETOT  (EE_ + NN_)
#define H_    4
#define F_    256
#define HF_   1024
#define LEAKY 0.2f
#define CH    128
#define NTILE 79
#define TRI   (NTILE * (NTILE + 1) / 2)

// ---------------- scratch (device globals) ----------------------------------
__device__ float g_h[(size_t)NN_ * HF_];
__device__ float g_als[NN_ * H_];
__device__ float g_ald[NN_ * H_];
__device__ float g_act0[(size_t)NN_ * F_];
__device__ float g_zbuf[(size_t)NN_ * F_];
__device__ int   g_cnt[NN_];
__device__ int   g_off[NN_ + 1];
__device__ int   g_wpos[NN_];
__device__ int   g_srcs[ETOT];
__device__ __align__(16) __nv_bfloat16 g_bfh[(size_t)NN_ * F_];
__device__ __align__(16) __nv_bfloat16 g_bfl[(size_t)NN_ * F_];
__device__ __align__(16) __nv_bfloat16 g_wth[(size_t)HF_ * F_];
__device__ __align__(16) __nv_bfloat16 g_wtl[(size_t)HF_ * F_];

// ---------------- small PTX helpers -----------------------------------------
__device__ __forceinline__ uint32_t smem_u32(const void* p) {
    uint32_t a;
    asm("{ .reg .u64 t; cvta.to.shared.u64 t, %1; cvt.u32.u64 %0, t; }" : "=r"(a) : "l"(p));
    return a;
}
__device__ __forceinline__ void cp16(uint32_t dst, const void* src, bool valid) {
    int sz = valid ? 16 : 0;
    asm volatile("cp.async.cg.shared.global [%0], [%1], 16, %2;"
                 :: "r"(dst), "l"(src), "r"(sz) : "memory");
}
__device__ __forceinline__ void cp_commit() {
    asm volatile("cp.async.commit_group;" ::: "memory");
}
__device__ __forceinline__ void cp_wait1() {
    asm volatile("cp.async.wait_group 1;" ::: "memory");
}
__device__ __forceinline__ void ldsm4(uint32_t& r0, uint32_t& r1, uint32_t& r2,
                                      uint32_t& r3, uint32_t a) {
    asm volatile("ldmatrix.sync.aligned.m8n8.x4.shared.b16 {%0,%1,%2,%3}, [%4];"
                 : "=r"(r0), "=r"(r1), "=r"(r2), "=r"(r3) : "r"(a));
}
__device__ __forceinline__ void mma16816(float c[4], uint32_t a0, uint32_t a1,
                                         uint32_t a2, uint32_t a3,
                                         uint32_t b0, uint32_t b1) {
    asm volatile(
        "mma.sync.aligned.m16n8k16.row.col.f32.bf16.bf16.f32 "
        "{%0,%1,%2,%3}, {%4,%5,%6,%7}, {%8,%9}, {%0,%1,%2,%3};"
        : "+f"(c[0]), "+f"(c[1]), "+f"(c[2]), "+f"(c[3])
        : "r"(a0), "r"(a1), "r"(a2), "r"(a3), "r"(b0), "r"(b1));
}

// ---------------- CSR build -------------------------------------------------
__global__ void zero_int2() {
    int i = blockIdx.x * blockDim.x + threadIdx.x;
    if (i < NN_) { g_cnt[i] = 0; g_wpos[i] = 0; }
}
__global__ void count_kernel(const int* __restrict__ ei) {
    int e = blockIdx.x * blockDim.x + threadIdx.x;
    if (e >= ETOT) return;
    int dst = (e < EE_) ? ei[EE_ + e] : (e - EE_);
    atomicAdd(&g_cnt[dst], 1);
}
__global__ void scan_kernel() {
    __shared__ int sh[1024];
    int tid = threadIdx.x;
    int carry = 0;
    for (int base = 0; base < NN_; base += 1024) {
        int v = (base + tid < NN_) ? g_cnt[base + tid] : 0;
        sh[tid] = v;
        __syncthreads();
        for (int d = 1; d < 1024; d <<= 1) {
            int t = (tid >= d) ? sh[tid - d] : 0;
            __syncthreads();
            sh[tid] += t;
            __syncthreads();
        }
        if (base + tid < NN_) g_off[base + tid] = carry + sh[tid] - v;
        int tot = sh[1023];
        __syncthreads();
        carry += tot;
    }
    if (tid == 0) g_off[NN_] = carry;
}
__global__ void scatter_kernel(const int* __restrict__ ei) {
    int e = blockIdx.x * blockDim.x + threadIdx.x;
    if (e >= ETOT) return;
    int src, dst;
    if (e < EE_) { src = ei[e]; dst = ei[EE_ + e]; }
    else         { src = e - EE_; dst = e - EE_; }
    int pos = g_off[dst] + atomicAdd(&g_wpos[dst], 1);
    g_srcs[pos] = src;
}
__global__ void zero_attn() {
    int i = blockIdx.x * blockDim.x + threadIdx.x;
    if (i < NN_ * H_) { g_als[i] = 0.f; g_ald[i] = 0.f; }
}

// ---------------- unified bf16-split HMMA GEMM (3-stage pipeline) -----------
#define GBUF   32768
#define NSTAGE 3

__global__ __launch_bounds__(256) void hmma_tt(
    const __nv_bfloat16* __restrict__ Ah, const __nv_bfloat16* __restrict__ Al,
    const __nv_bfloat16* __restrict__ Bh, const __nv_bfloat16* __restrict__ Bl,
    const float* __restrict__ asrc, const float* __restrict__ adst,
    float* __restrict__ C, int M, int Ncols, size_t ldc, int mode)
{
    extern __shared__ char dyn_smem[];
    uint32_t smem_base = smem_u32(dyn_smem);

    int tid = threadIdx.x;
    int wid = tid >> 5, lane = tid & 31;
    int wm = wid >> 2, wn = wid & 3;
    int g = lane >> 2, t = lane & 3;

    int bx, by;
    if (mode == 2) {
        int j = blockIdx.x;
        bx = (int)((sqrtf(8.f * j + 1.f) - 1.f) * 0.5f);
        while ((bx + 1) * (bx + 2) / 2 <= j) bx++;
        while (bx * (bx + 1) / 2 > j) bx--;
        by = j - bx * (bx + 1) / 2;
    } else {
        bx = blockIdx.x; by = blockIdx.y;
    }
    int m0 = by * 128, n0 = bx * 128;

    const __nv_bfloat16* segA[3] = { Ah, Ah, Al };
    const __nv_bfloat16* segB[3] = { Bh, Bl, Bh };

    // hoisted loader geometry (chunk-invariant): 4 transfers per tile per thread
    uint32_t l_off[4];       // swizzled smem byte offset
    size_t   l_arow[4], l_brow[4];   // row byte offsets into A/B (bf16*2 bytes)
    bool     l_va[4], l_vb[4];
#pragma unroll
    for (int i = 0; i < 4; i++) {
        int idx = tid + i * 256;
        int r = idx >> 3, s16 = idx & 7;
        l_off[i] = (uint32_t)(r * 128 + ((s16 ^ (r & 7)) << 4));
        int gm = m0 + r, gn = n0 + r;
        l_va[i] = gm < M;
        l_vb[i] = gn < Ncols;
        l_arow[i] = (size_t)(l_va[i] ? gm : 0) * (F_ * 2) + (size_t)s16 * 16;
        l_brow[i] = (size_t)(l_vb[i] ? gn : 0) * (F_ * 2) + (size_t)s16 * 16;
    }

    float acc[4][4][4];
#pragma unroll
    for (int i = 0; i < 4; i++)
#pragma unroll
        for (int j2 = 0; j2 < 4; j2++)
#pragma unroll
            for (int k = 0; k < 4; k++) acc[i][j2][k] = 0.f;

    auto issue_chunk = [&](int c) {
        int seg = c >> 2;
        size_t kb = (size_t)((c & 3) * 64) * 2;   // k0 bytes
        const char* As = (const char*)segA[seg] + kb;
        const char* Bs = (const char*)segB[seg] + kb;
        uint32_t sa = smem_base + (c % NSTAGE) * GBUF;
        uint32_t sb = sa + 16384;
#pragma unroll
        for (int i = 0; i < 4; i++) {
            cp16(sa + l_off[i], As + l_arow[i], l_va[i]);
            cp16(sb + l_off[i], Bs + l_brow[i], l_vb[i]);
        }
        cp_commit();
    };

    issue_chunk(0);
    issue_chunk(1);

    int lr = lane & 15;
    // hoisted fragment address pieces
    uint32_t a_rowoff[4], b_rowoff[2];
    uint32_t rxa = (uint32_t)(lr & 7) << 4, lhalf = (uint32_t)(lane >> 4) << 4;
#pragma unroll
    for (int mt = 0; mt < 4; mt++)
        a_rowoff[mt] = (uint32_t)((wm * 64 + mt * 16 + lr) * 128);
#pragma unroll
    for (int hb = 0; hb < 2; hb++)
        b_rowoff[hb] = (uint32_t)((wn * 32 + hb * 16 + lr) * 128);

    for (int c = 0; c < 12; c++) {
        cp_wait1();
        __syncthreads();
        if (c + 2 < 12) issue_chunk(c + 2);

        uint32_t sa = smem_base + (c % NSTAGE) * GBUF;
        uint32_t sb = sa + 16384;
#pragma unroll
        for (int ks = 0; ks < 4; ks++) {
            uint32_t xr = ((uint32_t)(2 * ks) << 4) + lhalf;  // lseg<<4 pre-xor
            uint32_t af[4][4];
#pragma unroll
            for (int mt = 0; mt < 4; mt++)
                ldsm4(af[mt][0], af[mt][1], af[mt][2], af[mt][3],
                      sa + a_rowoff[mt] + (xr ^ rxa));
            uint32_t bq[2][4];
#pragma unroll
            for (int hb = 0; hb < 2; hb++)
                ldsm4(bq[hb][0], bq[hb][1], bq[hb][2], bq[hb][3],
                      sb + b_rowoff[hb] + (xr ^ rxa));
#pragma unroll
            for (int mt = 0; mt < 4; mt++)
#pragma unroll
                for (int nt = 0; nt < 4; nt++)
                    mma16816(acc[mt][nt],
                             af[mt][0], af[mt][1], af[mt][2], af[mt][3],
                             bq[nt >> 1][nt & 1], bq[nt >> 1][(nt & 1) + 2]);
        }
    }

    if (mode == 0) {
        int head = n0 >> 8;
        int base = n0 & 255;
        float a0v[4], a1v[4], b0v[4], b1v[4];
#pragma unroll
        for (int nt = 0; nt < 4; nt++) {
            int f = head * 256 + base + wn * 32 + nt * 8 + 2 * t;
            a0v[nt] = asrc[f];  a1v[nt] = asrc[f + 1];
            b0v[nt] = adst[f];  b1v[nt] = adst[f + 1];
        }
#pragma unroll
        for (int mt = 0; mt < 4; mt++) {
            int gm = m0 + wm * 64 + mt * 16 + g;
            float s0 = 0.f, s1 = 0.f, d0 = 0.f, d1 = 0.f;
#pragma unroll
            for (int nt = 0; nt < 4; nt++) {
                int gn = n0 + wn * 32 + nt * 8 + 2 * t;
                float* p0 = C + (size_t)gm * ldc + gn;
                if (gm < M)
                    *reinterpret_cast<float2*>(p0) =
                        make_float2(acc[mt][nt][0], acc[mt][nt][1]);
                if (gm + 8 < M)
                    *reinterpret_cast<float2*>(p0 + 8 * ldc) =
                        make_float2(acc[mt][nt][2], acc[mt][nt][3]);
                s0 += acc[mt][nt][0] * a0v[nt] + acc[mt][nt][1] * a1v[nt];
                s1 += acc[mt][nt][2] * a0v[nt] + acc[mt][nt][3] * a1v[nt];
                d0 += acc[mt][nt][0] * b0v[nt] + acc[mt][nt][1] * b1v[nt];
                d1 += acc[mt][nt][2] * b0v[nt] + acc[mt][nt][3] * b1v[nt];
            }
#pragma unroll
            for (int o = 1; o <= 2; o <<= 1) {
                s0 += __shfl_xor_sync(0xffffffffu, s0, o);
                s1 += __shfl_xor_sync(0xffffffffu, s1, o);
                d0 += __shfl_xor_sync(0xffffffffu, d0, o);
                d1 += __shfl_xor_sync(0xffffffffu, d1, o);
            }
            if (t == 0) {
                if (gm < M) {
                    atomicAdd(&g_als[gm * H_ + head], s0);
                    atomicAdd(&g_ald[gm * H_ + head], d0);
                }
                if (gm + 8 < M) {
                    atomicAdd(&g_als[(gm + 8) * H_ + head], s1);
                    atomicAdd(&g_ald[(gm + 8) * H_ + head], d1);
                }
            }
        }
    } else {
        bool mirror = (bx != by);
#pragma unroll
        for (int mt = 0; mt < 4; mt++) {
            int gm = m0 + wm * 64 + mt * 16 + g;
#pragma unroll
            for (int nt = 0; nt < 4; nt++) {
                int gn = n0 + wn * 32 + nt * 8 + 2 * t;
                if (gn >= Ncols) continue;
                float* p0 = C + (size_t)gm * ldc + gn;
                float s0 = 1.f / (1.f + __expf(-acc[mt][nt][0]));
                float s1 = 1.f / (1.f + __expf(-acc[mt][nt][1]));
                float s2 = 1.f / (1.f + __expf(-acc[mt][nt][2]));
                float s3 = 1.f / (1.f + __expf(-acc[mt][nt][3]));
                if (gm < M)
                    *reinterpret_cast<float2*>(p0) = make_float2(s0, s1);
                if (gm + 8 < M)
                    *reinterpret_cast<float2*>(p0 + 8 * ldc) = make_float2(s2, s3);
                if (mirror) {
                    float* q0 = C + (size_t)gn * ldc;
                    float* q1 = C + (size_t)(gn + 1) * ldc;
                    if (gm < M)     { q0[gm] = s0;     q1[gm] = s1; }
                    if (gm + 8 < M) { q0[gm + 8] = s2; q1[gm + 8] = s3; }
                }
            }
        }
    }
}

// ---------------- W transpose + hi/lo split ---------------------------------
__global__ void wt_split(const float* __restrict__ W) {
    __shared__ float tbuf[32][33];
    int bx = blockIdx.x, by = blockIdx.y;
    int x = threadIdx.x, y = threadIdx.y;
    for (int i = y; i < 32; i += 8)
        tbuf[i][x] = W[(size_t)(by * 32 + i) * HF_ + bx * 32 + x];
    __syncthreads();
    for (int i = y; i < 32; i += 8) {
        float v = tbuf[x][i];
        __nv_bfloat16 h = __float2bfloat16(v);
        size_t o = (size_t)(bx * 32 + i) * F_ + by * 32 + x;
        g_wth[o] = h;
        g_wtl[o] = __float2bfloat16(v - __bfloat162float(h));
    }
}

// ---------------- x -> bf16 hi/lo -------------------------------------------
__global__ void split_x(const float* __restrict__ x) {
    int i = blockIdx.x * blockDim.x + threadIdx.x;
    if (i >= NN_ * F_) return;
    float v = x[i];
    __nv_bfloat16 h = __float2bfloat16(v);
    g_bfh[i] = h;
    g_bfl[i] = __float2bfloat16(v - __bfloat162float(h));
}

// ---------------- per-dst online softmax + aggregation ----------------------
__device__ __forceinline__ float leaky(float x) {
    return x > 0.f ? x : LEAKY * x;
}

__global__ __launch_bounds__(256) void aggregate(
    const float* __restrict__ bias, float* __restrict__ xout, int mode)
{
    __shared__ float swm[8][H_], sws[8][H_];
    __shared__ float s_m[H_], s_inv[H_];
    __shared__ float alpha_sh[CH][H_];
    __shared__ int   src_sh[CH];

    int n = blockIdx.x, tid = threadIdx.x;
    int wid = tid >> 5, lane = tid & 31;
    int beg = g_off[n];
    int deg = g_off[n + 1] - beg;

    float ald[H_];
#pragma unroll
    for (int h = 0; h < H_; h++) ald[h] = g_ald[n * H_ + h];

    float m[H_], s[H_];
#pragma unroll
    for (int h = 0; h < H_; h++) { m[h] = -1e30f; s[h] = 0.f; }
    for (int i = tid; i < deg; i += 256) {
        int sc = g_srcs[beg + i];
#pragma unroll
        for (int h = 0; h < H_; h++) {
            float e = leaky(g_als[sc * H_ + h] + ald[h]);
            if (e > m[h]) { s[h] = s[h] * __expf(m[h] - e) + 1.f; m[h] = e; }
            else          s[h] += __expf(e - m[h]);
        }
    }
#pragma unroll
    for (int o = 16; o; o >>= 1) {
#pragma unroll
        for (int h = 0; h < H_; h++) {
            float mo = __shfl_down_sync(0xffffffffu, m[h], o);
            float so = __shfl_down_sync(0xffffffffu, s[h], o);
            float mn = fmaxf(m[h], mo);
            s[h] = s[h] * __expf(m[h] - mn) + so * __expf(mo - mn);
            m[h] = mn;
        }
    }
    if (lane == 0)
#pragma unroll
        for (int h = 0; h < H_; h++) { swm[wid][h] = m[h]; sws[wid][h] = s[h]; }
    __syncthreads();
    if (tid < 32) {
        bool v = lane < 8;
#pragma unroll
        for (int h = 0; h < H_; h++) {
            m[h] = v ? swm[lane][h] : -1e30f;
            s[h] = v ? sws[lane][h] : 0.f;
        }
#pragma unroll
        for (int o = 4; o; o >>= 1) {
#pragma unroll
            for (int h = 0; h < H_; h++) {
                float mo = __shfl_down_sync(0xffffffffu, m[h], o);
                float so = __shfl_down_sync(0xffffffffu, s[h], o);
                float mn = fmaxf(m[h], mo);
                s[h] = s[h] * __expf(m[h] - mn) + so * __expf(mo - mn);
                m[h] = mn;
            }
        }
        if (lane == 0)
#pragma unroll
            for (int h = 0; h < H_; h++) {
                s_m[h]   = m[h];
                s_inv[h] = 1.f / (s[h] + 1e-16f);
            }
    }
    __syncthreads();

    float sm_r[H_], si_r[H_];
#pragma unroll
    for (int h = 0; h < H_; h++) { sm_r[h] = s_m[h]; si_r[h] = s_inv[h]; }

    float acc[H_] = {0.f, 0.f, 0.f, 0.f};
    for (int base = 0; base < deg; base += CH) {
        int c = min(CH, deg - base);
        __syncthreads();
        for (int i = tid; i < c; i += 256) {
            int sc = g_srcs[beg + base + i];
            src_sh[i] = sc;
#pragma unroll
            for (int h = 0; h < H_; h++) {
                float e = leaky(g_als[sc * H_ + h] + ald[h]);
                alpha_sh[i][h] = __expf(e - sm_r[h]) * si_r[h];
            }
        }
        __syncthreads();
        int j = 0;
        for (; j + 4 <= c; j += 4) {
            int s0 = src_sh[j],     s1 = src_sh[j + 1];
            int s2 = src_sh[j + 2], s3 = src_sh[j + 3];
            const float* h0 = &g_h[(size_t)s0 * HF_ + tid];
            const float* h1 = &g_h[(size_t)s1 * HF_ + tid];
            const float* h2 = &g_h[(size_t)s2 * HF_ + tid];
            const float* h3 = &g_h[(size_t)s3 * HF_ + tid];
#pragma unroll
            for (int h = 0; h < H_; h++) {
                acc[h] += alpha_sh[j][h]     * h0[h * F_]
                        + alpha_sh[j + 1][h] * h1[h * F_]
                        + alpha_sh[j + 2][h] * h2[h * F_]
                        + alpha_sh[j + 3][h] * h3[h * F_];
            }
        }
        for (; j < c; j++) {
            int s0 = src_sh[j];
            const float* h0 = &g_h[(size_t)s0 * HF_ + tid];
#pragma unroll
            for (int h = 0; h < H_; h++)
                acc[h] += alpha_sh[j][h] * h0[h * F_];
        }
    }

    float v = (acc[0] + acc[1] + acc[2] + acc[3]) * 0.25f + bias[tid];
    v = mode ? tanhf(v) : fmaxf(v, 0.f);
    size_t o = (size_t)n * F_ + tid;
    xout[o] = v;
    __nv_bfloat16 hh = __float2bfloat16(v);
    g_bfh[o] = hh;
    g_bfl[o] = __float2bfloat16(v - __bfloat162float(hh));
}

// ---------------- driver ----------------------------------------------------
extern "C" void kernel_launch(void* const* d_in, const int* in_sizes, int n_in,
                              void* d_out, int out_size)
{
    const float* x  = (const float*)d_in[0];
    const int*   ei = (const int*)d_in[1];
    const float* W[4];  const float* as_[4]; const float* ad_[4]; const float* b_[4];
    for (int l = 0; l < 4; l++) {
        W[l]   = (const float*)d_in[2 + 4 * l];
        as_[l] = (const float*)d_in[3 + 4 * l];
        ad_[l] = (const float*)d_in[4 + 4 * l];
        b_[l]  = (const float*)d_in[5 + 4 * l];
    }
    float* out = (float*)d_out;

    float *p_h, *p_act0, *p_z;
    __nv_bfloat16 *p_bfh, *p_bfl, *p_wth, *p_wtl;
    cudaGetSymbolAddress((void**)&p_h,    g_h);
    cudaGetSymbolAddress((void**)&p_act0, g_act0);
    cudaGetSymbolAddress((void**)&p_z,    g_zbuf);
    cudaGetSymbolAddress((void**)&p_bfh,  g_bfh);
    cudaGetSymbolAddress((void**)&p_bfl,  g_bfl);
    cudaGetSymbolAddress((void**)&p_wth,  g_wth);
    cudaGetSymbolAddress((void**)&p_wtl,  g_wtl);

    const size_t ADJ = (size_t)NN_ * NN_;
    bool z_in_out = ((size_t)out_size >= ADJ + (size_t)NN_ * F_);
    float* zptr = z_in_out ? (out + ADJ) : p_z;

    static bool smem_attr = false;
    if (!smem_attr) {
        cudaFuncSetAttribute(hmma_tt, cudaFuncAttributeMaxDynamicSharedMemorySize,
                             NSTAGE * GBUF);
        smem_attr = true;
    }

    dim3 lgrid(HF_ / 128, (NN_ + 127) / 128);

    // ---- layer 0 front (hmma_tt is 4th launch -> ncu target) ----
    split_x<<<(NN_ * F_ + 255) / 256, 256>>>(x);
    wt_split<<<dim3(32, 8), dim3(32, 8)>>>(W[0]);
    zero_attn<<<(NN_ * H_ + 255) / 256, 256>>>();
    hmma_tt<<<lgrid, 256, NSTAGE * GBUF>>>(p_bfh, p_bfl, p_wth, p_wtl,
                                           as_[0], ad_[0], p_h, NN_, HF_, HF_, 0);

    // ---- CSR build ----
    zero_int2<<<(NN_ + 255) / 256, 256>>>();
    count_kernel<<<(ETOT + 255) / 256, 256>>>(ei);
    scan_kernel<<<1, 1024>>>();
    scatter_kernel<<<(ETOT + 255) / 256, 256>>>(ei);

    aggregate<<<NN_, 256>>>(b_[0], p_act0, 0);

    // ---- layers 1..3 ----
    for (int l = 1; l < 4; l++) {
        wt_split<<<dim3(32, 8), dim3(32, 8)>>>(W[l]);
        zero_attn<<<(NN_ * H_ + 255) / 256, 256>>>();
        hmma_tt<<<lgrid, 256, NSTAGE * GBUF>>>(p_bfh, p_bfl, p_wth, p_wtl,
                                               as_[l], ad_[l], p_h, NN_, HF_, HF_, 0);
        aggregate<<<NN_, 256>>>(b_[l], (l == 3) ? zptr : p_act0, (l == 3) ? 1 : 0);
    }

    // ---- adj_recon = sigmoid(z @ z^T), triangular grid + mirror ----
    hmma_tt<<<TRI, 256, NSTAGE * GBUF>>>(p_bfh, p_bfl, p_bfh, p_bfl,
                                         nullptr, nullptr, out, NN_, NN_, NN_, 2);
}